// round 1
// baseline (speedup 1.0000x reference)
#include <cuda_runtime.h>
#include <math.h>

#define S 2048
#define VDIM 1024
#define NH 16
#define DH 64

// ---------------- scratch (device globals: allocation-guard safe) ----------
__device__ float g_qkv[S * 3 * VDIM];                       // [2048,3072]
__device__ float g_relproj[S * VDIM];                       // [2048,1024]
__device__ float g_AD[(size_t)NH * S * S];                  // content logits -> scores (in place)
__device__ float g_QP[(size_t)NH * S * S];                  // positional logits (unshifted)
__device__ float g_attn[S * VDIM];                          // [2048,1024] P@V merged heads

// ---------------------------------------------------------------------------
// Generic batched NT SGEMM: C[m,n] = sum_k (A[m,k]+bias[k]) * B[n,k]
// Tiles: 128x128x16, 256 threads, 8x8 microtile. Grid covers exact dims.
// Batch (blockIdx.z) applies element offsets aStride/bStride/cStride/biasStride.
// ---------------------------------------------------------------------------
__global__ __launch_bounds__(256)
void sgemm_nt(const float* __restrict__ A, int lda, long aStride,
              const float* __restrict__ B, int ldb, long bStride,
              float* __restrict__ C, int ldc, long cStride,
              int K,
              const float* __restrict__ bias, long biasStride)
{
    const int BK = 16;
    const int bz = blockIdx.z;
    A += (long)bz * aStride;
    B += (long)bz * bStride;
    C += (long)bz * cStride;
    const float* biasp = bias ? (bias + (long)bz * biasStride) : nullptr;

    __shared__ float As[BK][128];
    __shared__ float Bs[BK][128];

    const int tid = threadIdx.x;
    const long row0 = (long)blockIdx.y * 128;
    const long col0 = (long)blockIdx.x * 128;

    const int lr = tid >> 2;          // 0..63
    const int lk = (tid & 3) * 4;     // 0,4,8,12

    const int tr = (tid >> 4) * 8;    // 0..120
    const int tc = (tid & 15) * 8;    // 0..120

    float acc[8][8];
#pragma unroll
    for (int i = 0; i < 8; i++)
#pragma unroll
        for (int j = 0; j < 8; j++) acc[i][j] = 0.f;

    for (int k0 = 0; k0 < K; k0 += BK) {
        float bb0 = 0.f, bb1 = 0.f, bb2 = 0.f, bb3 = 0.f;
        if (biasp) {
            bb0 = biasp[k0 + lk + 0];
            bb1 = biasp[k0 + lk + 1];
            bb2 = biasp[k0 + lk + 2];
            bb3 = biasp[k0 + lk + 3];
        }
#pragma unroll
        for (int l = 0; l < 2; l++) {
            const int r = lr + l * 64;
            const float4 va = *(const float4*)&A[(row0 + r) * lda + k0 + lk];
            As[lk + 0][r] = va.x + bb0;
            As[lk + 1][r] = va.y + bb1;
            As[lk + 2][r] = va.z + bb2;
            As[lk + 3][r] = va.w + bb3;
            const float4 vb = *(const float4*)&B[(col0 + r) * ldb + k0 + lk];
            Bs[lk + 0][r] = vb.x;
            Bs[lk + 1][r] = vb.y;
            Bs[lk + 2][r] = vb.z;
            Bs[lk + 3][r] = vb.w;
        }
        __syncthreads();
#pragma unroll
        for (int k = 0; k < BK; k++) {
            const float4 a0 = *(const float4*)&As[k][tr];
            const float4 a1 = *(const float4*)&As[k][tr + 4];
            const float4 b0 = *(const float4*)&Bs[k][tc];
            const float4 b1 = *(const float4*)&Bs[k][tc + 4];
            const float a[8] = {a0.x, a0.y, a0.z, a0.w, a1.x, a1.y, a1.z, a1.w};
            const float b[8] = {b0.x, b0.y, b0.z, b0.w, b1.x, b1.y, b1.z, b1.w};
#pragma unroll
            for (int i = 0; i < 8; i++)
#pragma unroll
                for (int j = 0; j < 8; j++)
                    acc[i][j] = fmaf(a[i], b[j], acc[i][j]);
        }
        __syncthreads();
    }

#pragma unroll
    for (int i = 0; i < 8; i++) {
#pragma unroll
        for (int j = 0; j < 8; j += 4) {
            float4 v = make_float4(acc[i][j], acc[i][j + 1], acc[i][j + 2], acc[i][j + 3]);
            *(float4*)&C[(row0 + tr + i) * ldc + col0 + tc + j] = v;
        }
    }
}

// ---------------------------------------------------------------------------
// Fused shift-gather + causal mask + softmax (in-place on AD -> probs).
// One block per (row i, head h). 256 threads, 8 elems/thread in registers.
//   logits[j] = (AD[i,j] + QP[i,(j-i-1) mod S]) / sqrt(D), j <= i; masked else.
// ---------------------------------------------------------------------------
__global__ __launch_bounds__(256)
void softmax_shift(float* __restrict__ AD, const float* __restrict__ QP)
{
    const int i = blockIdx.x;
    const int h = blockIdx.y;
    float* ad = AD + ((long)h * S + i) * S;
    const float* qp = QP + ((long)h * S + i) * S;

    __shared__ float red[8];

    const int tid = threadIdx.x;
    const int lane = tid & 31, warp = tid >> 5;

    float buf[8];
    float lmax = -1e30f;
#pragma unroll
    for (int t = 0; t < 8; t++) {
        const int j = tid + t * 256;
        float v = -1e30f;
        if (j <= i) {
            const int jj = (j - i - 1 + S) & (S - 1);
            v = (ad[j] + qp[jj]) * 0.125f;   // 1/sqrt(64)
        }
        buf[t] = v;
        lmax = fmaxf(lmax, v);
    }
#pragma unroll
    for (int o = 16; o; o >>= 1) lmax = fmaxf(lmax, __shfl_xor_sync(0xffffffffu, lmax, o));
    if (lane == 0) red[warp] = lmax;
    __syncthreads();
    float m = red[0];
#pragma unroll
    for (int w = 1; w < 8; w++) m = fmaxf(m, red[w]);
    __syncthreads();

    float lsum = 0.f;
#pragma unroll
    for (int t = 0; t < 8; t++) {
        const int j = tid + t * 256;
        float e = (j <= i) ? __expf(buf[t] - m) : 0.f;
        buf[t] = e;
        lsum += e;
    }
#pragma unroll
    for (int o = 16; o; o >>= 1) lsum += __shfl_xor_sync(0xffffffffu, lsum, o);
    if (lane == 0) red[warp] = lsum;
    __syncthreads();
    float s = 0.f;
#pragma unroll
    for (int w = 0; w < 8; w++) s += red[w];
    const float inv = 1.f / s;

#pragma unroll
    for (int t = 0; t < 8; t++) {
        const int j = tid + t * 256;
        ad[j] = buf[t] * inv;
    }
}

// ---------------------------------------------------------------------------
// P @ V per head (NN GEMM): C[i, 64h+d] = sum_j P[h,i,j] * v[j, 64h+d]
// A = probs [S,S] row-major (K-inner), B = qkv v-slice (ldb=3V), N=64.
// Tiles 128x64x16, 256 threads, 8x4 microtile.
// ---------------------------------------------------------------------------
__global__ __launch_bounds__(256)
void sgemm_nn_pv(const float* __restrict__ A,
                 const float* __restrict__ B,
                 float* __restrict__ C)
{
    const int BK = 16;
    const int h = blockIdx.z;
    const float* Ah = A + (long)h * S * S;
    const float* Bh = B + h * DH;
    float* Ch = C + h * DH;

    __shared__ float As[BK][128];
    __shared__ float Bs[BK][64];

    const int tid = threadIdx.x;
    const long row0 = (long)blockIdx.y * 128;

    const int lr = tid >> 2;          // 0..63
    const int lk = (tid & 3) * 4;
    const int br = tid >> 4;          // 0..15  (k row of B tile)
    const int bc = (tid & 15) * 4;    // 0..60

    const int tr = (tid >> 4) * 8;
    const int tc = (tid & 15) * 4;

    float acc[8][4];
#pragma unroll
    for (int i = 0; i < 8; i++)
#pragma unroll
        for (int j = 0; j < 4; j++) acc[i][j] = 0.f;

    for (int k0 = 0; k0 < S; k0 += BK) {
#pragma unroll
        for (int l = 0; l < 2; l++) {
            const int r = lr + l * 64;
            const float4 va = *(const float4*)&Ah[(row0 + r) * S + k0 + lk];
            As[lk + 0][r] = va.x;
            As[lk + 1][r] = va.y;
            As[lk + 2][r] = va.z;
            As[lk + 3][r] = va.w;
        }
        {
            const float4 vb = *(const float4*)&Bh[(long)(k0 + br) * (3 * VDIM) + bc];
            Bs[br][bc + 0] = vb.x;
            Bs[br][bc + 1] = vb.y;
            Bs[br][bc + 2] = vb.z;
            Bs[br][bc + 3] = vb.w;
        }
        __syncthreads();
#pragma unroll
        for (int k = 0; k < BK; k++) {
            const float4 a0 = *(const float4*)&As[k][tr];
            const float4 a1 = *(const float4*)&As[k][tr + 4];
            const float4 b0 = *(const float4*)&Bs[k][tc];
            const float a[8] = {a0.x, a0.y, a0.z, a0.w, a1.x, a1.y, a1.z, a1.w};
            const float b[4] = {b0.x, b0.y, b0.z, b0.w};
#pragma unroll
            for (int i = 0; i < 8; i++)
#pragma unroll
                for (int j = 0; j < 4; j++)
                    acc[i][j] = fmaf(a[i], b[j], acc[i][j]);
        }
        __syncthreads();
    }

#pragma unroll
    for (int i = 0; i < 8; i++) {
        float4 v = make_float4(acc[i][0], acc[i][1], acc[i][2], acc[i][3]);
        *(float4*)&Ch[(row0 + tr + i) * VDIM + tc] = v;
    }
}

// ---------------------------------------------------------------------------
extern "C" void kernel_launch(void* const* d_in, const int* in_sizes, int n_in,
                              void* d_out, int out_size)
{
    const float* x    = (const float*)d_in[0];   // [1,2048,1024]
    const float* Wqkv = (const float*)d_in[1];   // [3072,1024]
    const float* Wout = (const float*)d_in[2];   // [1024,1024]
    const float* Wpos = (const float*)d_in[3];   // [1024,1024]
    const float* uvec = (const float*)d_in[4];   // [1,16,1,64]
    const float* vvec = (const float*)d_in[5];   // [1,16,1,64]
    const float* rel  = (const float*)d_in[6];   // [2048,1024]
    float* out = (float*)d_out;

    float *qkv, *relproj, *AD, *QP, *attn;
    cudaGetSymbolAddress((void**)&qkv,     g_qkv);
    cudaGetSymbolAddress((void**)&relproj, g_relproj);
    cudaGetSymbolAddress((void**)&AD,      g_AD);
    cudaGetSymbolAddress((void**)&QP,      g_QP);
    cudaGetSymbolAddress((void**)&attn,    g_attn);

    const dim3 blk(256);
    const long SS = (long)S * S;

    // 1) qkv = x @ Wqkv^T               [2048,3072]
    sgemm_nt<<<dim3(3072 / 128, S / 128, 1), blk>>>(
        x, VDIM, 0, Wqkv, VDIM, 0, qkv, 3 * VDIM, 0, VDIM, nullptr, 0);

    // 2) relproj = rel @ Wpos^T         [2048,1024]  (relproj[j,64h+d] == rel[h,d,j])
    sgemm_nt<<<dim3(VDIM / 128, S / 128, 1), blk>>>(
        rel, VDIM, 0, Wpos, VDIM, 0, relproj, VDIM, 0, VDIM, nullptr, 0);

    // 3) AD[h] = (q_h + u_h) @ k_h^T    [16,2048,2048]
    sgemm_nt<<<dim3(S / 128, S / 128, NH), blk>>>(
        qkv, 3 * VDIM, DH, qkv + VDIM, 3 * VDIM, DH, AD, S, SS, DH, uvec, DH);

    // 4) QP[h] = (q_h + v_h) @ rel_h^T  [16,2048,2048]
    sgemm_nt<<<dim3(S / 128, S / 128, NH), blk>>>(
        qkv, 3 * VDIM, DH, relproj, VDIM, DH, QP, S, SS, DH, vvec, DH);

    // 5) shift-gather + causal softmax (in place on AD)
    softmax_shift<<<dim3(S, NH), blk>>>(AD, QP);

    // 6) attn = P @ v                   [2048,1024] merged-head layout
    sgemm_nn_pv<<<dim3(1, S / 128, NH), blk>>>(AD, qkv + 2 * VDIM, attn);

    // 7) out = attn @ Wout^T            [2048,1024]
    sgemm_nt<<<dim3(VDIM / 128, S / 128, 1), blk>>>(
        attn, VDIM, 0, Wout, VDIM, 0, out, VDIM, 0, VDIM, nullptr, 0);
}

// round 3
// speedup vs baseline: 2.8746x; 2.8746x over previous
#include <cuda_runtime.h>
#include <cstdint>
#include <math.h>

#define S 2048
#define VDIM 1024
#define NH 16
#define DH 64

// ---------------- scratch (device globals) ---------------------------------
__device__ float g_xr[S * VDIM];
__device__ float g_wqkvr[3 * VDIM * VDIM];
__device__ float g_woutr[VDIM * VDIM];
__device__ float g_wposr[VDIM * VDIM];
__device__ float g_relr[S * VDIM];
__device__ float g_qkv[S * 3 * VDIM];
__device__ float g_relproj[S * VDIM];
__device__ float g_qu[S * VDIM];
__device__ float g_qv[S * VDIM];
__device__ float g_vt[VDIM * S];
__device__ float g_AD[(size_t)NH * S * S];
__device__ float g_QP[(size_t)NH * S * S];
__device__ float g_attn[S * VDIM];

// ---------------- helpers ---------------------------------------------------
__device__ __forceinline__ uint32_t cvta_smem(const void* p) {
    uint32_t a;
    asm("{ .reg .u64 t; cvta.to.shared.u64 t, %1; cvt.u32.u64 %0, t; }" : "=r"(a) : "l"(p));
    return a;
}
__device__ __forceinline__ float rna_tf32(float f) {
    uint32_t u;
    asm("cvt.rna.tf32.f32 %0, %1;" : "=r"(u) : "f"(f));
    return __uint_as_float(u);
}
#define CP16(smem_u32, gptr) \
    asm volatile("cp.async.cg.shared.global [%0], [%1], 16;" :: "r"(smem_u32), "l"(gptr) : "memory")
#define CP_COMMIT() asm volatile("cp.async.commit_group;" ::: "memory")

__device__ __forceinline__ void mma_tf32_16x8x8(float* c, const uint32_t* a, const uint32_t* b) {
    asm volatile(
        "mma.sync.aligned.m16n8k8.row.col.f32.tf32.tf32.f32 "
        "{%0,%1,%2,%3}, {%4,%5,%6,%7}, {%8,%9}, {%0,%1,%2,%3};"
        : "+f"(c[0]), "+f"(c[1]), "+f"(c[2]), "+f"(c[3])
        : "r"(a[0]), "r"(a[1]), "r"(a[2]), "r"(a[3]), "r"(b[0]), "r"(b[1]));
}

// ---------------------------------------------------------------------------
// tf32 mma.sync NT GEMM: C[m,n] = sum_k A[m,k]*B[n,k]
// BM=128, BN in {128,64}, BK=32, 3-stage cp.async pipeline, 256 threads.
// MODE: 0 = full grid (bx,by); 1 = lower-triangular tiles (br>=bc);
//       2 = anti-upper tiles (br+bc>=15). KROW: limit K to BM*(br+1).
// ---------------------------------------------------------------------------
#define BKC 32
#define STG 3
#define APITCH 36

template <int BN, int MODE, bool KROW, bool ROUND>
__global__ __launch_bounds__(256, 1)
void mma_gemm_nt(const float* __restrict__ A, int lda, long aStride,
                 const float* __restrict__ B, int ldb, long bStride,
                 float* __restrict__ C, int ldc, long cStride, int K)
{
    constexpr int BM = 128;
    constexpr int A_ST = BM * APITCH;          // floats per A stage
    constexpr int B_ST = BN * APITCH;
    extern __shared__ float smf[];
    float* As = smf;                            // [STG][BM][APITCH]
    float* Bs = smf + STG * A_ST;               // [STG][BN][APITCH]
    const uint32_t sA0 = cvta_smem(As);
    const uint32_t sB0 = cvta_smem(Bs);

    int br, bc;
    if (MODE == 0) {
        br = blockIdx.y; bc = blockIdx.x;
    } else {
        int t = blockIdx.x;
        int r = (int)((sqrtf(8.f * (float)t + 1.f) - 1.f) * 0.5f);
        while ((r + 1) * (r + 2) / 2 <= t) r++;
        while (r * (r + 1) / 2 > t) r--;
        int j = t - r * (r + 1) / 2;
        br = r;
        bc = (MODE == 1) ? j : (15 - r + j);
    }
    const int bz = blockIdx.z;
    A += (long)bz * aStride;
    B += (long)bz * bStride;
    C += (long)bz * cStride;
    const long row0 = (long)br * BM;
    const long col0 = (long)bc * BN;

    int K_run = K;
    if (KROW) { int kl = BM * (br + 1); if (kl < K_run) K_run = kl; }
    const int NC = K_run / BKC;

    const int tid = threadIdx.x;
    const int wid = tid >> 5, lane = tid & 31;
    const int lq = lane >> 2, lr = lane & 3;

    const int wm0 = (BN == 128) ? (wid >> 2) * 64 : (wid >> 1) * 32;
    const int wn0 = (BN == 128) ? (wid & 3) * 32 : (wid & 1) * 32;
    constexpr int MT = (BN == 128) ? 4 : 2;
    constexpr int NT = 4;

    float acc[MT][NT][4];
#pragma unroll
    for (int i = 0; i < MT; i++)
#pragma unroll
        for (int j = 0; j < NT; j++)
#pragma unroll
            for (int q = 0; q < 4; q++) acc[i][j][q] = 0.f;

    auto load_stage = [&](int c) {
        const int s = c % STG;
        const int k0 = c * BKC;
#pragma unroll
        for (int t4 = 0; t4 < 4; t4++) {
            int idx = tid + t4 * 256;
            int row = idx >> 3, kc = idx & 7;
            const float* g = A + (row0 + row) * (long)lda + k0 + kc * 4;
            CP16(sA0 + (uint32_t)(s * A_ST * 4 + row * 144 + kc * 16), g);
        }
#pragma unroll
        for (int t4 = 0; t4 < (BN == 128 ? 4 : 2); t4++) {
            int idx = tid + t4 * 256;
            int row = idx >> 3, kc = idx & 7;
            const float* g = B + (col0 + row) * (long)ldb + k0 + kc * 4;
            CP16(sB0 + (uint32_t)(s * B_ST * 4 + row * 144 + kc * 16), g);
        }
        CP_COMMIT();
    };

    const int PRO = (NC < STG - 1) ? NC : (STG - 1);
    for (int c = 0; c < PRO; c++) load_stage(c);

    for (int c = 0; c < NC; c++) {
        int n = NC - 1 - c;
        if (n > STG - 2) n = STG - 2;
        if (n == 0) asm volatile("cp.async.wait_group 0;" ::: "memory");
        else        asm volatile("cp.async.wait_group 1;" ::: "memory");
        __syncthreads();
        if (c + STG - 1 < NC) load_stage(c + STG - 1);

        const float* aS = As + (c % STG) * A_ST;
        const float* bS = Bs + (c % STG) * B_ST;
#pragma unroll
        for (int ks = 0; ks < 4; ks++) {
            const int kk = ks * 8;
            uint32_t af[MT][4];
            uint32_t bf[NT][2];
#pragma unroll
            for (int mt = 0; mt < MT; mt++) {
                const int m = wm0 + mt * 16 + lq;
                af[mt][0] = __float_as_uint(aS[m * APITCH + kk + lr]);
                af[mt][1] = __float_as_uint(aS[(m + 8) * APITCH + kk + lr]);
                af[mt][2] = __float_as_uint(aS[m * APITCH + kk + 4 + lr]);
                af[mt][3] = __float_as_uint(aS[(m + 8) * APITCH + kk + 4 + lr]);
            }
#pragma unroll
            for (int nt = 0; nt < NT; nt++) {
                const int nn = wn0 + nt * 8 + lq;
                bf[nt][0] = __float_as_uint(bS[nn * APITCH + kk + lr]);
                bf[nt][1] = __float_as_uint(bS[nn * APITCH + kk + 4 + lr]);
            }
#pragma unroll
            for (int mt = 0; mt < MT; mt++)
#pragma unroll
                for (int nt = 0; nt < NT; nt++)
                    mma_tf32_16x8x8(acc[mt][nt], af[mt], bf[nt]);
        }
        __syncthreads();
    }

    // epilogue
#pragma unroll
    for (int mt = 0; mt < MT; mt++) {
        const long r0 = row0 + wm0 + mt * 16 + lq;
#pragma unroll
        for (int nt = 0; nt < NT; nt++) {
            const int cc = (int)col0 + wn0 + nt * 8 + 2 * lr;
            float2 v0 = make_float2(acc[mt][nt][0], acc[mt][nt][1]);
            float2 v1 = make_float2(acc[mt][nt][2], acc[mt][nt][3]);
            if (ROUND) {
                v0.x = rna_tf32(v0.x); v0.y = rna_tf32(v0.y);
                v1.x = rna_tf32(v1.x); v1.y = rna_tf32(v1.y);
            }
            *(float2*)&C[r0 * ldc + cc] = v0;
            *(float2*)&C[(r0 + 8) * ldc + cc] = v1;
        }
    }
}

// ---------------------------------------------------------------------------
// aux kernels
// ---------------------------------------------------------------------------
__global__ void round_tf32_k(const float* __restrict__ in, float* __restrict__ out, int n) {
    int i = (blockIdx.x * blockDim.x + threadIdx.x) * 4;
    if (i < n) {
        float4 v = *(const float4*)(in + i);
        v.x = rna_tf32(v.x); v.y = rna_tf32(v.y);
        v.z = rna_tf32(v.z); v.w = rna_tf32(v.w);
        *(float4*)(out + i) = v;
    }
}

__global__ void make_quqv(const float* __restrict__ qkv, const float* __restrict__ u,
                          const float* __restrict__ v, float* __restrict__ qu,
                          float* __restrict__ qv) {
    int i = blockIdx.x * blockDim.x + threadIdx.x;   // over S*VDIM
    int r = i >> 10, c = i & 1023;
    float q = qkv[r * 3072 + c];
    qu[i] = rna_tf32(q + u[c]);
    qv[i] = rna_tf32(q + v[c]);
}

__global__ void transpose_v(const float* __restrict__ qkv, float* __restrict__ vt) {
    __shared__ float t[32][33];
    const int j0 = blockIdx.x * 32, c0 = blockIdx.y * 32;
    const int tx = threadIdx.x, ty = threadIdx.y;
#pragma unroll
    for (int k = 0; k < 32; k += 8)
        t[ty + k][tx] = qkv[(long)(j0 + ty + k) * 3072 + 2 * VDIM + c0 + tx];
    __syncthreads();
#pragma unroll
    for (int k = 0; k < 32; k += 8)
        vt[(long)(c0 + ty + k) * S + j0 + tx] = t[tx][ty + k];
}

// fused shift-gather + causal mask + softmax, writes tf32-rounded probs in place
__global__ __launch_bounds__(256)
void softmax_shift(float* __restrict__ AD, const float* __restrict__ QP) {
    const int i = blockIdx.x;
    const int h = blockIdx.y;
    float* ad = AD + ((long)h * S + i) * S;
    const float* qp = QP + ((long)h * S + i) * S;

    __shared__ float red[8];
    const int tid = threadIdx.x;
    const int lane = tid & 31, warp = tid >> 5;

    float buf[8];
    float lmax = -1e30f;
#pragma unroll
    for (int t = 0; t < 8; t++) {
        const int j = tid + t * 256;
        float v = -1e30f;
        if (j <= i) {
            const int jj = (j - i - 1 + S) & (S - 1);
            v = (ad[j] + qp[jj]) * 0.125f;
        }
        buf[t] = v;
        lmax = fmaxf(lmax, v);
    }
#pragma unroll
    for (int o = 16; o; o >>= 1) lmax = fmaxf(lmax, __shfl_xor_sync(0xffffffffu, lmax, o));
    if (lane == 0) red[warp] = lmax;
    __syncthreads();
    float m = red[0];
#pragma unroll
    for (int w = 1; w < 8; w++) m = fmaxf(m, red[w]);
    __syncthreads();

    float lsum = 0.f;
#pragma unroll
    for (int t = 0; t < 8; t++) {
        const int j = tid + t * 256;
        float e = (j <= i) ? __expf(buf[t] - m) : 0.f;
        buf[t] = e;
        lsum += e;
    }
#pragma unroll
    for (int o = 16; o; o >>= 1) lsum += __shfl_xor_sync(0xffffffffu, lsum, o);
    if (lane == 0) red[warp] = lsum;
    __syncthreads();
    float sm = 0.f;
#pragma unroll
    for (int w = 0; w < 8; w++) sm += red[w];
    const float inv = 1.f / sm;

#pragma unroll
    for (int t = 0; t < 8; t++) {
        const int j = tid + t * 256;
        ad[j] = rna_tf32(buf[t] * inv);
    }
}

// ---------------------------------------------------------------------------
extern "C" void kernel_launch(void* const* d_in, const int* in_sizes, int n_in,
                              void* d_out, int out_size)
{
    const float* x    = (const float*)d_in[0];
    const float* Wqkv = (const float*)d_in[1];
    const float* Wout = (const float*)d_in[2];
    const float* Wpos = (const float*)d_in[3];
    const float* uvec = (const float*)d_in[4];
    const float* vvec = (const float*)d_in[5];
    const float* rel  = (const float*)d_in[6];
    float* out = (float*)d_out;

    float *xr, *wqkvr, *woutr, *wposr, *relr, *qkv, *relproj, *qu, *qv, *vt, *AD, *QP, *attn;
    cudaGetSymbolAddress((void**)&xr,      g_xr);
    cudaGetSymbolAddress((void**)&wqkvr,   g_wqkvr);
    cudaGetSymbolAddress((void**)&woutr,   g_woutr);
    cudaGetSymbolAddress((void**)&wposr,   g_wposr);
    cudaGetSymbolAddress((void**)&relr,    g_relr);
    cudaGetSymbolAddress((void**)&qkv,     g_qkv);
    cudaGetSymbolAddress((void**)&relproj, g_relproj);
    cudaGetSymbolAddress((void**)&qu,      g_qu);
    cudaGetSymbolAddress((void**)&qv,      g_qv);
    cudaGetSymbolAddress((void**)&vt,      g_vt);
    cudaGetSymbolAddress((void**)&AD,      g_AD);
    cudaGetSymbolAddress((void**)&QP,      g_QP);
    cudaGetSymbolAddress((void**)&attn,    g_attn);

    const int SMEM128 = STG * (128 + 128) * APITCH * 4;   // 110592
    const int SMEM64  = STG * (128 + 64) * APITCH * 4;    //  82944
    static bool attr_done = false;
    if (!attr_done) {
        cudaFuncSetAttribute(mma_gemm_nt<128, 0, false, true>,
                             cudaFuncAttributeMaxDynamicSharedMemorySize, SMEM128);
        cudaFuncSetAttribute(mma_gemm_nt<128, 0, false, false>,
                             cudaFuncAttributeMaxDynamicSharedMemorySize, SMEM128);
        cudaFuncSetAttribute(mma_gemm_nt<128, 1, false, false>,
                             cudaFuncAttributeMaxDynamicSharedMemorySize, SMEM128);
        cudaFuncSetAttribute(mma_gemm_nt<128, 2, false, false>,
                             cudaFuncAttributeMaxDynamicSharedMemorySize, SMEM128);
        cudaFuncSetAttribute(mma_gemm_nt<64, 0, true, true>,
                             cudaFuncAttributeMaxDynamicSharedMemorySize, SMEM64);
        attr_done = true;
    }

    const long SS = (long)S * S;

    // 0) round inputs to tf32 (rna)
    round_tf32_k<<<(S * VDIM) / 1024, 256>>>(x, xr, S * VDIM);
    round_tf32_k<<<(3 * VDIM * VDIM) / 1024, 256>>>(Wqkv, wqkvr, 3 * VDIM * VDIM);
    round_tf32_k<<<(VDIM * VDIM) / 1024, 256>>>(Wout, woutr, VDIM * VDIM);
    round_tf32_k<<<(VDIM * VDIM) / 1024, 256>>>(Wpos, wposr, VDIM * VDIM);
    round_tf32_k<<<(S * VDIM) / 1024, 256>>>(rel, relr, S * VDIM);

    // 1) qkv = x @ Wqkv^T
    mma_gemm_nt<128, 0, false, true><<<dim3(24, 16, 1), 256, SMEM128>>>(
        xr, VDIM, 0, wqkvr, VDIM, 0, qkv, 3 * VDIM, 0, VDIM);

    // 2) relproj = rel @ Wpos^T
    mma_gemm_nt<128, 0, false, true><<<dim3(8, 16, 1), 256, SMEM128>>>(
        relr, VDIM, 0, wposr, VDIM, 0, relproj, VDIM, 0, VDIM);

    // 3) qu = q + u, qv = q + v   (tf32-rounded)
    make_quqv<<<(S * VDIM) / 256, 256>>>(qkv, uvec, vvec, qu, qv);

    // 3b) VT[h*64+d][j] = v[j][64h+d]
    transpose_v<<<dim3(S / 32, VDIM / 32), dim3(32, 8)>>>(qkv, vt);

    // 4) AD[h] = qu_h @ k_h^T  (lower-triangular tiles only)
    mma_gemm_nt<128, 1, false, false><<<dim3(136, 1, 16), 256, SMEM128>>>(
        qu, VDIM, DH, qkv + VDIM, 3 * VDIM, DH, AD, S, SS, DH);

    // 5) QP[h] = qv_h @ rel_h^T  (anti-upper tiles only)
    mma_gemm_nt<128, 2, false, false><<<dim3(136, 1, 16), 256, SMEM128>>>(
        qv, VDIM, DH, relproj, VDIM, DH, QP, S, SS, DH);

    // 6) shift + causal softmax (in place, tf32-rounded probs)
    softmax_shift<<<dim3(S, NH), 256>>>(AD, QP);

    // 7) attn = P @ V  (NT vs VT, K limited per row block)
    mma_gemm_nt<64, 0, true, true><<<dim3(1, 16, 16), 256, SMEM64>>>(
        AD, S, SS, vt, S, (long)DH * S, attn, VDIM, DH, S);

    // 8) out = attn @ Wout^T
    mma_gemm_nt<128, 0, false, false><<<dim3(8, 16, 1), 256, SMEM128>>>(
        attn, VDIM, 0, woutr, VDIM, 0, out, VDIM, 0, VDIM);
}

// round 4
// speedup vs baseline: 2.8749x; 1.0001x over previous
#include <cuda_runtime.h>
#include <cstdint>
#include <math.h>

#define S 2048
#define VDIM 1024
#define NH 16
#define DH 64

// ---------------- scratch (device globals) ---------------------------------
__device__ float g_xr[S * VDIM];
__device__ float g_wqkvr[3 * VDIM * VDIM];
__device__ float g_woutr[VDIM * VDIM];
__device__ float g_wposr[VDIM * VDIM];
__device__ float g_relr[S * VDIM];
__device__ float g_qkv[S * 3 * VDIM];
__device__ float g_relproj[S * VDIM];
__device__ float g_qu[S * VDIM];
__device__ float g_qv[S * VDIM];
__device__ float g_vt[VDIM * S];
__device__ float g_AD[(size_t)NH * S * S];
__device__ float g_QP[(size_t)NH * S * S];
__device__ float g_attn[S * VDIM];

// ---------------- helpers ---------------------------------------------------
__device__ __forceinline__ uint32_t cvta_smem(const void* p) {
    uint32_t a;
    asm("{ .reg .u64 t; cvta.to.shared.u64 t, %1; cvt.u32.u64 %0, t; }" : "=r"(a) : "l"(p));
    return a;
}
__device__ __forceinline__ float rna_tf32(float f) {
    uint32_t u;
    asm("cvt.rna.tf32.f32 %0, %1;" : "=r"(u) : "f"(f));
    return __uint_as_float(u);
}
#define CP16(smem_u32, gptr) \
    asm volatile("cp.async.cg.shared.global [%0], [%1], 16;" :: "r"(smem_u32), "l"(gptr) : "memory")
#define CP_COMMIT() asm volatile("cp.async.commit_group;" ::: "memory")

__device__ __forceinline__ void mma_tf32_16x8x8(float* c, const uint32_t* a, const uint32_t* b) {
    asm volatile(
        "mma.sync.aligned.m16n8k8.row.col.f32.tf32.tf32.f32 "
        "{%0,%1,%2,%3}, {%4,%5,%6,%7}, {%8,%9}, {%0,%1,%2,%3};"
        : "+f"(c[0]), "+f"(c[1]), "+f"(c[2]), "+f"(c[3])
        : "r"(a[0]), "r"(a[1]), "r"(a[2]), "r"(a[3]), "r"(b[0]), "r"(b[1]));
}

// ---------------------------------------------------------------------------
// tf32 mma.sync NT GEMM: C[m,n] = sum_k A[m,k]*B[n,k]
// BM=128, BN in {128,64}, BK=32, 3-stage cp.async pipeline, 256 threads.
// MODE: 0 = full grid (bx,by); 1 = lower-triangular tiles (br>=bc);
//       2 = anti-upper tiles (br+bc>=15). KROW: limit K to BM*(br+1).
// ---------------------------------------------------------------------------
#define BKC 32
#define STG 3
#define APITCH 36

template <int BN, int MODE, bool KROW, bool ROUND>
__global__ __launch_bounds__(256, 1)
void mma_gemm_nt(const float* __restrict__ A, int lda, long aStride,
                 const float* __restrict__ B, int ldb, long bStride,
                 float* __restrict__ C, int ldc, long cStride, int K)
{
    constexpr int BM = 128;
    constexpr int A_ST = BM * APITCH;          // floats per A stage
    constexpr int B_ST = BN * APITCH;
    extern __shared__ float smf[];
    float* As = smf;                            // [STG][BM][APITCH]
    float* Bs = smf + STG * A_ST;               // [STG][BN][APITCH]
    const uint32_t sA0 = cvta_smem(As);
    const uint32_t sB0 = cvta_smem(Bs);

    int br, bc;
    if (MODE == 0) {
        br = blockIdx.y; bc = blockIdx.x;
    } else {
        int t = blockIdx.x;
        int r = (int)((sqrtf(8.f * (float)t + 1.f) - 1.f) * 0.5f);
        while ((r + 1) * (r + 2) / 2 <= t) r++;
        while (r * (r + 1) / 2 > t) r--;
        int j = t - r * (r + 1) / 2;
        br = r;
        bc = (MODE == 1) ? j : (15 - r + j);
    }
    const int bz = blockIdx.z;
    A += (long)bz * aStride;
    B += (long)bz * bStride;
    C += (long)bz * cStride;
    const long row0 = (long)br * BM;
    const long col0 = (long)bc * BN;

    int K_run = K;
    if (KROW) { int kl = BM * (br + 1); if (kl < K_run) K_run = kl; }
    const int NC = K_run / BKC;

    const int tid = threadIdx.x;
    const int wid = tid >> 5, lane = tid & 31;
    const int lq = lane >> 2, lr = lane & 3;

    const int wm0 = (BN == 128) ? (wid >> 2) * 64 : (wid >> 1) * 32;
    const int wn0 = (BN == 128) ? (wid & 3) * 32 : (wid & 1) * 32;
    constexpr int MT = (BN == 128) ? 4 : 2;
    constexpr int NT = 4;

    float acc[MT][NT][4];
#pragma unroll
    for (int i = 0; i < MT; i++)
#pragma unroll
        for (int j = 0; j < NT; j++)
#pragma unroll
            for (int q = 0; q < 4; q++) acc[i][j][q] = 0.f;

    auto load_stage = [&](int c) {
        const int s = c % STG;
        const int k0 = c * BKC;
#pragma unroll
        for (int t4 = 0; t4 < 4; t4++) {
            int idx = tid + t4 * 256;
            int row = idx >> 3, kc = idx & 7;
            const float* g = A + (row0 + row) * (long)lda + k0 + kc * 4;
            CP16(sA0 + (uint32_t)(s * A_ST * 4 + row * 144 + kc * 16), g);
        }
#pragma unroll
        for (int t4 = 0; t4 < (BN == 128 ? 4 : 2); t4++) {
            int idx = tid + t4 * 256;
            int row = idx >> 3, kc = idx & 7;
            const float* g = B + (col0 + row) * (long)ldb + k0 + kc * 4;
            CP16(sB0 + (uint32_t)(s * B_ST * 4 + row * 144 + kc * 16), g);
        }
        CP_COMMIT();
    };

    const int PRO = (NC < STG - 1) ? NC : (STG - 1);
    for (int c = 0; c < PRO; c++) load_stage(c);

    for (int c = 0; c < NC; c++) {
        int n = NC - 1 - c;
        if (n > STG - 2) n = STG - 2;
        if (n == 0) asm volatile("cp.async.wait_group 0;" ::: "memory");
        else        asm volatile("cp.async.wait_group 1;" ::: "memory");
        __syncthreads();
        if (c + STG - 1 < NC) load_stage(c + STG - 1);

        const float* aS = As + (c % STG) * A_ST;
        const float* bS = Bs + (c % STG) * B_ST;
#pragma unroll
        for (int ks = 0; ks < 4; ks++) {
            const int kk = ks * 8;
            uint32_t af[MT][4];
            uint32_t bf[NT][2];
#pragma unroll
            for (int mt = 0; mt < MT; mt++) {
                const int m = wm0 + mt * 16 + lq;
                af[mt][0] = __float_as_uint(aS[m * APITCH + kk + lr]);
                af[mt][1] = __float_as_uint(aS[(m + 8) * APITCH + kk + lr]);
                af[mt][2] = __float_as_uint(aS[m * APITCH + kk + 4 + lr]);
                af[mt][3] = __float_as_uint(aS[(m + 8) * APITCH + kk + 4 + lr]);
            }
#pragma unroll
            for (int nt = 0; nt < NT; nt++) {
                const int nn = wn0 + nt * 8 + lq;
                bf[nt][0] = __float_as_uint(bS[nn * APITCH + kk + lr]);
                bf[nt][1] = __float_as_uint(bS[nn * APITCH + kk + 4 + lr]);
            }
#pragma unroll
            for (int mt = 0; mt < MT; mt++)
#pragma unroll
                for (int nt = 0; nt < NT; nt++)
                    mma_tf32_16x8x8(acc[mt][nt], af[mt], bf[nt]);
        }
        __syncthreads();
    }

    // epilogue
#pragma unroll
    for (int mt = 0; mt < MT; mt++) {
        const long r0 = row0 + wm0 + mt * 16 + lq;
#pragma unroll
        for (int nt = 0; nt < NT; nt++) {
            const int cc = (int)col0 + wn0 + nt * 8 + 2 * lr;
            float2 v0 = make_float2(acc[mt][nt][0], acc[mt][nt][1]);
            float2 v1 = make_float2(acc[mt][nt][2], acc[mt][nt][3]);
            if (ROUND) {
                v0.x = rna_tf32(v0.x); v0.y = rna_tf32(v0.y);
                v1.x = rna_tf32(v1.x); v1.y = rna_tf32(v1.y);
            }
            *(float2*)&C[r0 * ldc + cc] = v0;
            *(float2*)&C[(r0 + 8) * ldc + cc] = v1;
        }
    }
}

// ---------------------------------------------------------------------------
// aux kernels
// ---------------------------------------------------------------------------
__global__ void round_tf32_k(const float* __restrict__ in, float* __restrict__ out, int n) {
    int i = (blockIdx.x * blockDim.x + threadIdx.x) * 4;
    if (i < n) {
        float4 v = *(const float4*)(in + i);
        v.x = rna_tf32(v.x); v.y = rna_tf32(v.y);
        v.z = rna_tf32(v.z); v.w = rna_tf32(v.w);
        *(float4*)(out + i) = v;
    }
}

__global__ void make_quqv(const float* __restrict__ qkv, const float* __restrict__ u,
                          const float* __restrict__ v, float* __restrict__ qu,
                          float* __restrict__ qv) {
    int i = blockIdx.x * blockDim.x + threadIdx.x;   // over S*VDIM
    int r = i >> 10, c = i & 1023;
    float q = qkv[r * 3072 + c];
    qu[i] = rna_tf32(q + u[c]);
    qv[i] = rna_tf32(q + v[c]);
}

__global__ void transpose_v(const float* __restrict__ qkv, float* __restrict__ vt) {
    __shared__ float t[32][33];
    const int j0 = blockIdx.x * 32, c0 = blockIdx.y * 32;
    const int tx = threadIdx.x, ty = threadIdx.y;
#pragma unroll
    for (int k = 0; k < 32; k += 8)
        t[ty + k][tx] = qkv[(long)(j0 + ty + k) * 3072 + 2 * VDIM + c0 + tx];
    __syncthreads();
#pragma unroll
    for (int k = 0; k < 32; k += 8)
        vt[(long)(c0 + ty + k) * S + j0 + tx] = t[tx][ty + k];
}

// fused shift-gather + causal mask + softmax, writes tf32-rounded probs in place
__global__ __launch_bounds__(256)
void softmax_shift(float* __restrict__ AD, const float* __restrict__ QP) {
    const int i = blockIdx.x;
    const int h = blockIdx.y;
    float* ad = AD + ((long)h * S + i) * S;
    const float* qp = QP + ((long)h * S + i) * S;

    __shared__ float red[8];
    const int tid = threadIdx.x;
    const int lane = tid & 31, warp = tid >> 5;

    float buf[8];
    float lmax = -1e30f;
#pragma unroll
    for (int t = 0; t < 8; t++) {
        const int j = tid + t * 256;
        float v = -1e30f;
        if (j <= i) {
            const int jj = (j - i - 1 + S) & (S - 1);
            v = (ad[j] + qp[jj]) * 0.125f;
        }
        buf[t] = v;
        lmax = fmaxf(lmax, v);
    }
#pragma unroll
    for (int o = 16; o; o >>= 1) lmax = fmaxf(lmax, __shfl_xor_sync(0xffffffffu, lmax, o));
    if (lane == 0) red[warp] = lmax;
    __syncthreads();
    float m = red[0];
#pragma unroll
    for (int w = 1; w < 8; w++) m = fmaxf(m, red[w]);
    __syncthreads();

    float lsum = 0.f;
#pragma unroll
    for (int t = 0; t < 8; t++) {
        const int j = tid + t * 256;
        float e = (j <= i) ? __expf(buf[t] - m) : 0.f;
        buf[t] = e;
        lsum += e;
    }
#pragma unroll
    for (int o = 16; o; o >>= 1) lsum += __shfl_xor_sync(0xffffffffu, lsum, o);
    if (lane == 0) red[warp] = lsum;
    __syncthreads();
    float sm = 0.f;
#pragma unroll
    for (int w = 0; w < 8; w++) sm += red[w];
    const float inv = 1.f / sm;

#pragma unroll
    for (int t = 0; t < 8; t++) {
        const int j = tid + t * 256;
        ad[j] = rna_tf32(buf[t] * inv);
    }
}

// ---------------------------------------------------------------------------
extern "C" void kernel_launch(void* const* d_in, const int* in_sizes, int n_in,
                              void* d_out, int out_size)
{
    const float* x    = (const float*)d_in[0];
    const float* Wqkv = (const float*)d_in[1];
    const float* Wout = (const float*)d_in[2];
    const float* Wpos = (const float*)d_in[3];
    const float* uvec = (const float*)d_in[4];
    const float* vvec = (const float*)d_in[5];
    const float* rel  = (const float*)d_in[6];
    float* out = (float*)d_out;

    float *xr, *wqkvr, *woutr, *wposr, *relr, *qkv, *relproj, *qu, *qv, *vt, *AD, *QP, *attn;
    cudaGetSymbolAddress((void**)&xr,      g_xr);
    cudaGetSymbolAddress((void**)&wqkvr,   g_wqkvr);
    cudaGetSymbolAddress((void**)&woutr,   g_woutr);
    cudaGetSymbolAddress((void**)&wposr,   g_wposr);
    cudaGetSymbolAddress((void**)&relr,    g_relr);
    cudaGetSymbolAddress((void**)&qkv,     g_qkv);
    cudaGetSymbolAddress((void**)&relproj, g_relproj);
    cudaGetSymbolAddress((void**)&qu,      g_qu);
    cudaGetSymbolAddress((void**)&qv,      g_qv);
    cudaGetSymbolAddress((void**)&vt,      g_vt);
    cudaGetSymbolAddress((void**)&AD,      g_AD);
    cudaGetSymbolAddress((void**)&QP,      g_QP);
    cudaGetSymbolAddress((void**)&attn,    g_attn);

    const int SMEM128 = STG * (128 + 128) * APITCH * 4;   // 110592
    const int SMEM64  = STG * (128 + 64) * APITCH * 4;    //  82944
    static bool attr_done = false;
    if (!attr_done) {
        cudaFuncSetAttribute(mma_gemm_nt<128, 0, false, true>,
                             cudaFuncAttributeMaxDynamicSharedMemorySize, SMEM128);
        cudaFuncSetAttribute(mma_gemm_nt<128, 0, false, false>,
                             cudaFuncAttributeMaxDynamicSharedMemorySize, SMEM128);
        cudaFuncSetAttribute(mma_gemm_nt<128, 1, false, false>,
                             cudaFuncAttributeMaxDynamicSharedMemorySize, SMEM128);
        cudaFuncSetAttribute(mma_gemm_nt<128, 2, false, false>,
                             cudaFuncAttributeMaxDynamicSharedMemorySize, SMEM128);
        cudaFuncSetAttribute(mma_gemm_nt<64, 0, true, true>,
                             cudaFuncAttributeMaxDynamicSharedMemorySize, SMEM64);
        attr_done = true;
    }

    const long SS = (long)S * S;

    // 0) round inputs to tf32 (rna)
    round_tf32_k<<<(S * VDIM) / 1024, 256>>>(x, xr, S * VDIM);
    round_tf32_k<<<(3 * VDIM * VDIM) / 1024, 256>>>(Wqkv, wqkvr, 3 * VDIM * VDIM);
    round_tf32_k<<<(VDIM * VDIM) / 1024, 256>>>(Wout, woutr, VDIM * VDIM);
    round_tf32_k<<<(VDIM * VDIM) / 1024, 256>>>(Wpos, wposr, VDIM * VDIM);
    round_tf32_k<<<(S * VDIM) / 1024, 256>>>(rel, relr, S * VDIM);

    // 1) qkv = x @ Wqkv^T
    mma_gemm_nt<128, 0, false, true><<<dim3(24, 16, 1), 256, SMEM128>>>(
        xr, VDIM, 0, wqkvr, VDIM, 0, qkv, 3 * VDIM, 0, VDIM);

    // 2) relproj = rel @ Wpos^T
    mma_gemm_nt<128, 0, false, true><<<dim3(8, 16, 1), 256, SMEM128>>>(
        relr, VDIM, 0, wposr, VDIM, 0, relproj, VDIM, 0, VDIM);

    // 3) qu = q + u, qv = q + v   (tf32-rounded)
    make_quqv<<<(S * VDIM) / 256, 256>>>(qkv, uvec, vvec, qu, qv);

    // 3b) VT[h*64+d][j] = v[j][64h+d]
    transpose_v<<<dim3(S / 32, VDIM / 32), dim3(32, 8)>>>(qkv, vt);

    // 4) AD[h] = qu_h @ k_h^T  (lower-triangular tiles only)
    mma_gemm_nt<128, 1, false, false><<<dim3(136, 1, 16), 256, SMEM128>>>(
        qu, VDIM, DH, qkv + VDIM, 3 * VDIM, DH, AD, S, SS, DH);

    // 5) QP[h] = qv_h @ rel_h^T  (anti-upper tiles only)
    mma_gemm_nt<128, 2, false, false><<<dim3(136, 1, 16), 256, SMEM128>>>(
        qv, VDIM, DH, relproj, VDIM, DH, QP, S, SS, DH);

    // 6) shift + causal softmax (in place, tf32-rounded probs)
    softmax_shift<<<dim3(S, NH), 256>>>(AD, QP);

    // 7) attn = P @ V  (NT vs VT, K limited per row block)
    mma_gemm_nt<64, 0, true, true><<<dim3(1, 16, 16), 256, SMEM64>>>(
        AD, S, SS, vt, S, (long)DH * S, attn, VDIM, DH, S);

    // 8) out = attn @ Wout^T
    mma_gemm_nt<128, 0, false, false><<<dim3(8, 16, 1), 256, SMEM128>>>(
        attn, VDIM, 0, woutr, VDIM, 0, out, VDIM, 0, VDIM);
}

// round 8
// speedup vs baseline: 2.8916x; 1.0058x over previous
#include <cuda_runtime.h>
#include <cstdint>
#include <math.h>

#define S 2048
#define VDIM 1024
#define NH 16
#define DH 64

// ---------------- scratch (device globals) ---------------------------------
__device__ float g_xr[S * VDIM];
__device__ float g_wqkvr[3 * VDIM * VDIM];
__device__ float g_woutr[VDIM * VDIM];
__device__ float g_wposr[VDIM * VDIM];
__device__ float g_relr[S * VDIM];
__device__ float g_qkv[S * 3 * VDIM];
__device__ float g_relproj[S * VDIM];
__device__ float g_qu[S * VDIM];
__device__ float g_qv[S * VDIM];
__device__ float g_vt[VDIM * S];
__device__ float g_AD[(size_t)NH * S * S];
__device__ float g_QP[(size_t)NH * S * S];
__device__ float g_attn[S * VDIM];

// ---------------- helpers ---------------------------------------------------
__device__ __forceinline__ uint32_t cvta_smem(const void* p) {
    uint32_t a;
    asm("{ .reg .u64 t; cvta.to.shared.u64 t, %1; cvt.u32.u64 %0, t; }" : "=r"(a) : "l"(p));
    return a;
}
__device__ __forceinline__ float rna_tf32(float f) {
    uint32_t u;
    asm("cvt.rna.tf32.f32 %0, %1;" : "=r"(u) : "f"(f));
    return __uint_as_float(u);
}
#define CP16(smem_u32, gptr) \
    asm volatile("cp.async.cg.shared.global [%0], [%1], 16;" :: "r"(smem_u32), "l"(gptr) : "memory")
#define CP_COMMIT() asm volatile("cp.async.commit_group;" ::: "memory")

__device__ __forceinline__ void mma_tf32_16x8x8(float* c, const uint32_t* a, const uint32_t* b) {
    asm volatile(
        "mma.sync.aligned.m16n8k8.row.col.f32.tf32.tf32.f32 "
        "{%0,%1,%2,%3}, {%4,%5,%6,%7}, {%8,%9}, {%0,%1,%2,%3};"
        : "+f"(c[0]), "+f"(c[1]), "+f"(c[2]), "+f"(c[3])
        : "r"(a[0]), "r"(a[1]), "r"(a[2]), "r"(a[3]), "r"(b[0]), "r"(b[1]));
}

// ---------------------------------------------------------------------------
// tf32 mma.sync NT GEMM: C[m,n] = sum_k A[m,k]*B[n,k]
// BM=128, BN in {128,64}, BK=32, 3-stage cp.async pipeline, 256 threads.
// MODE: 0 = full grid (bx,by); 1 = lower-triangular tiles (br>=bc);
//       2 = anti-upper tiles (br+bc>=15). KROW: limit K to BM*(br+1).
// ---------------------------------------------------------------------------
#define BKC 32
#define STG 3
#define APITCH 36

template <int BN, int MODE, bool KROW, bool ROUND>
__global__ __launch_bounds__(256, 1)
void mma_gemm_nt(const float* __restrict__ A, int lda, long aStride,
                 const float* __restrict__ B, int ldb, long bStride,
                 float* __restrict__ C, int ldc, long cStride, int K)
{
    constexpr int BM = 128;
    constexpr int A_ST = BM * APITCH;          // floats per A stage
    constexpr int B_ST = BN * APITCH;
    extern __shared__ float smf[];
    float* As = smf;                            // [STG][BM][APITCH]
    float* Bs = smf + STG * A_ST;               // [STG][BN][APITCH]
    const uint32_t sA0 = cvta_smem(As);
    const uint32_t sB0 = cvta_smem(Bs);

    int br, bc;
    if (MODE == 0) {
        br = blockIdx.y; bc = blockIdx.x;
    } else {
        int t = blockIdx.x;
        int r = (int)((sqrtf(8.f * (float)t + 1.f) - 1.f) * 0.5f);
        while ((r + 1) * (r + 2) / 2 <= t) r++;
        while (r * (r + 1) / 2 > t) r--;
        int j = t - r * (r + 1) / 2;
        br = r;
        bc = (MODE == 1) ? j : (15 - r + j);
    }
    const int bz = blockIdx.z;
    A += (long)bz * aStride;
    B += (long)bz * bStride;
    C += (long)bz * cStride;
    const long row0 = (long)br * BM;
    const long col0 = (long)bc * BN;

    int K_run = K;
    if (KROW) { int kl = BM * (br + 1); if (kl < K_run) K_run = kl; }
    const int NC = K_run / BKC;

    const int tid = threadIdx.x;
    const int wid = tid >> 5, lane = tid & 31;
    const int lq = lane >> 2, lr = lane & 3;

    const int wm0 = (BN == 128) ? (wid >> 2) * 64 : (wid >> 1) * 32;
    const int wn0 = (BN == 128) ? (wid & 3) * 32 : (wid & 1) * 32;
    constexpr int MT = (BN == 128) ? 4 : 2;
    constexpr int NT = 4;

    float acc[MT][NT][4];
#pragma unroll
    for (int i = 0; i < MT; i++)
#pragma unroll
        for (int j = 0; j < NT; j++)
#pragma unroll
            for (int q = 0; q < 4; q++) acc[i][j][q] = 0.f;

    auto load_stage = [&](int c) {
        const int s = c % STG;
        const int k0 = c * BKC;
#pragma unroll
        for (int t4 = 0; t4 < 4; t4++) {
            int idx = tid + t4 * 256;
            int row = idx >> 3, kc = idx & 7;
            const float* g = A + (row0 + row) * (long)lda + k0 + kc * 4;
            CP16(sA0 + (uint32_t)(s * A_ST * 4 + row * 144 + kc * 16), g);
        }
#pragma unroll
        for (int t4 = 0; t4 < (BN == 128 ? 4 : 2); t4++) {
            int idx = tid + t4 * 256;
            int row = idx >> 3, kc = idx & 7;
            const float* g = B + (col0 + row) * (long)ldb + k0 + kc * 4;
            CP16(sB0 + (uint32_t)(s * B_ST * 4 + row * 144 + kc * 16), g);
        }
        CP_COMMIT();
    };

    const int PRO = (NC < STG - 1) ? NC : (STG - 1);
    for (int c = 0; c < PRO; c++) load_stage(c);

    for (int c = 0; c < NC; c++) {
        int n = NC - 1 - c;
        if (n > STG - 2) n = STG - 2;
        if (n == 0) asm volatile("cp.async.wait_group 0;" ::: "memory");
        else        asm volatile("cp.async.wait_group 1;" ::: "memory");
        __syncthreads();   // orders compute(c-1) before loads(c) reuse that buffer
        if (c + STG - 1 < NC) load_stage(c + STG - 1);

        const float* aS = As + (c % STG) * A_ST;
        const float* bS = Bs + (c % STG) * B_ST;
#pragma unroll
        for (int ks = 0; ks < 4; ks++) {
            const int kk = ks * 8;
            uint32_t af[MT][4];
            uint32_t bf[NT][2];
#pragma unroll
            for (int mt = 0; mt < MT; mt++) {
                const int m = wm0 + mt * 16 + lq;
                af[mt][0] = __float_as_uint(aS[m * APITCH + kk + lr]);
                af[mt][1] = __float_as_uint(aS[(m + 8) * APITCH + kk + lr]);
                af[mt][2] = __float_as_uint(aS[m * APITCH + kk + 4 + lr]);
                af[mt][3] = __float_as_uint(aS[(m + 8) * APITCH + kk + 4 + lr]);
            }
#pragma unroll
            for (int nt = 0; nt < NT; nt++) {
                const int nn = wn0 + nt * 8 + lq;
                bf[nt][0] = __float_as_uint(bS[nn * APITCH + kk + lr]);
                bf[nt][1] = __float_as_uint(bS[nn * APITCH + kk + 4 + lr]);
            }
#pragma unroll
            for (int mt = 0; mt < MT; mt++)
#pragma unroll
                for (int nt = 0; nt < NT; nt++)
                    mma_tf32_16x8x8(acc[mt][nt], af[mt], bf[nt]);
        }
    }

    // epilogue
#pragma unroll
    for (int mt = 0; mt < MT; mt++) {
        const long r0 = row0 + wm0 + mt * 16 + lq;
#pragma unroll
        for (int nt = 0; nt < NT; nt++) {
            const int cc = (int)col0 + wn0 + nt * 8 + 2 * lr;
            float2 v0 = make_float2(acc[mt][nt][0], acc[mt][nt][1]);
            float2 v1 = make_float2(acc[mt][nt][2], acc[mt][nt][3]);
            if (ROUND) {
                v0.x = rna_tf32(v0.x); v0.y = rna_tf32(v0.y);
                v1.x = rna_tf32(v1.x); v1.y = rna_tf32(v1.y);
            }
            *(float2*)&C[r0 * ldc + cc] = v0;
            *(float2*)&C[(r0 + 8) * ldc + cc] = v1;
        }
    }
}

// ---------------------------------------------------------------------------
// aux kernels
// ---------------------------------------------------------------------------
// single merged tf32-rounding pass over all 5 input buffers (float4 units)
#define RN_X   (S * VDIM / 4)             // 524288
#define RN_WQ  (3 * VDIM * VDIM / 4)      // 786432
#define RN_WO  (VDIM * VDIM / 4)          // 262144
#define RN_WP  (VDIM * VDIM / 4)
#define RN_RE  (S * VDIM / 4)
__global__ __launch_bounds__(256)
void round_all(const float* __restrict__ x, float* __restrict__ xr,
               const float* __restrict__ wq, float* __restrict__ wqr,
               const float* __restrict__ wo, float* __restrict__ wor,
               const float* __restrict__ wp, float* __restrict__ wpr,
               const float* __restrict__ re, float* __restrict__ rer)
{
    int i = blockIdx.x * blockDim.x + threadIdx.x;   // float4 index
    const float* src; float* dst;
    if (i < RN_X)                       { src = x;  dst = xr; }
    else if ((i -= RN_X) < RN_WQ)       { src = wq; dst = wqr; }
    else if ((i -= RN_WQ) < RN_WO)      { src = wo; dst = wor; }
    else if ((i -= RN_WO) < RN_WP)      { src = wp; dst = wpr; }
    else if ((i -= RN_WP) < RN_RE)      { src = re; dst = rer; }
    else return;
    float4 v = ((const float4*)src)[i];
    v.x = rna_tf32(v.x); v.y = rna_tf32(v.y);
    v.z = rna_tf32(v.z); v.w = rna_tf32(v.w);
    ((float4*)dst)[i] = v;
}
#define RN_TOT (RN_X + RN_WQ + RN_WO + RN_WP + RN_RE)

__global__ void make_quqv(const float* __restrict__ qkv, const float* __restrict__ u,
                          const float* __restrict__ v, float* __restrict__ qu,
                          float* __restrict__ qv) {
    int i = blockIdx.x * blockDim.x + threadIdx.x;   // over S*VDIM
    int r = i >> 10, c = i & 1023;
    float q = qkv[r * 3072 + c];
    qu[i] = rna_tf32(q + u[c]);
    qv[i] = rna_tf32(q + v[c]);
}

__global__ void transpose_v(const float* __restrict__ qkv, float* __restrict__ vt) {
    __shared__ float t[32][33];
    const int j0 = blockIdx.x * 32, c0 = blockIdx.y * 32;
    const int tx = threadIdx.x, ty = threadIdx.y;
#pragma unroll
    for (int k = 0; k < 32; k += 8)
        t[ty + k][tx] = qkv[(long)(j0 + ty + k) * 3072 + 2 * VDIM + c0 + tx];
    __syncthreads();
#pragma unroll
    for (int k = 0; k < 32; k += 8)
        vt[(long)(c0 + ty + k) * S + j0 + tx] = t[tx][ty + k];
}

// fused shift-gather + causal mask + softmax, in place on AD.
// Only processes ceil((i+1)/256) chunks of 256 columns (trip count uniform per
// block). Zero-fills masked lanes within touched chunks, which covers the
// K_run = 128*(br+1) range read by the KROW-limited PV GEMM.
__global__ __launch_bounds__(256)
void softmax_shift(float* __restrict__ AD, const float* __restrict__ QP) {
    const int i = blockIdx.x;
    const int h = blockIdx.y;
    float* ad = AD + ((long)h * S + i) * S;
    const float* qp = QP + ((long)h * S + i) * S;

    const int nT = (i >> 8) + 1;                 // chunks of 256 columns

    __shared__ float red[8];
    const int tid = threadIdx.x;
    const int lane = tid & 31, warp = tid >> 5;

    float buf[8];
    float lmax = -1e30f;
    for (int t = 0; t < nT; t++) {
        const int j = tid + t * 256;
        float v = -1e30f;
        if (j <= i) {
            const int jj = (j - i - 1 + S) & (S - 1);
            v = (ad[j] + qp[jj]) * 0.125f;
        }
        buf[t] = v;
        lmax = fmaxf(lmax, v);
    }
#pragma unroll
    for (int o = 16; o; o >>= 1) lmax = fmaxf(lmax, __shfl_xor_sync(0xffffffffu, lmax, o));
    if (lane == 0) red[warp] = lmax;
    __syncthreads();
    float m = red[0];
#pragma unroll
    for (int w = 1; w < 8; w++) m = fmaxf(m, red[w]);
    __syncthreads();

    float lsum = 0.f;
    for (int t = 0; t < nT; t++) {
        const int j = tid + t * 256;
        float e = (j <= i) ? __expf(buf[t] - m) : 0.f;
        buf[t] = e;
        lsum += e;
    }
#pragma unroll
    for (int o = 16; o; o >>= 1) lsum += __shfl_xor_sync(0xffffffffu, lsum, o);
    if (lane == 0) red[warp] = lsum;
    __syncthreads();
    float sm = 0.f;
#pragma unroll
    for (int w = 0; w < 8; w++) sm += red[w];
    const float inv = 1.f / sm;

    for (int t = 0; t < nT; t++) {
        const int j = tid + t * 256;
        ad[j] = rna_tf32(buf[t] * inv);
    }
}

// ---------------------------------------------------------------------------
extern "C" void kernel_launch(void* const* d_in, const int* in_sizes, int n_in,
                              void* d_out, int out_size)
{
    const float* x    = (const float*)d_in[0];
    const float* Wqkv = (const float*)d_in[1];
    const float* Wout = (const float*)d_in[2];
    const float* Wpos = (const float*)d_in[3];
    const float* uvec = (const float*)d_in[4];
    const float* vvec = (const float*)d_in[5];
    const float* rel  = (const float*)d_in[6];
    float* out = (float*)d_out;

    float *xr, *wqkvr, *woutr, *wposr, *relr, *qkv, *relproj, *qu, *qv, *vt, *AD, *QP, *attn;
    cudaGetSymbolAddress((void**)&xr,      g_xr);
    cudaGetSymbolAddress((void**)&wqkvr,   g_wqkvr);
    cudaGetSymbolAddress((void**)&woutr,   g_woutr);
    cudaGetSymbolAddress((void**)&wposr,   g_wposr);
    cudaGetSymbolAddress((void**)&relr,    g_relr);
    cudaGetSymbolAddress((void**)&qkv,     g_qkv);
    cudaGetSymbolAddress((void**)&relproj, g_relproj);
    cudaGetSymbolAddress((void**)&qu,      g_qu);
    cudaGetSymbolAddress((void**)&qv,      g_qv);
    cudaGetSymbolAddress((void**)&vt,      g_vt);
    cudaGetSymbolAddress((void**)&AD,      g_AD);
    cudaGetSymbolAddress((void**)&QP,      g_QP);
    cudaGetSymbolAddress((void**)&attn,    g_attn);

    const int SMEM128 = STG * (128 + 128) * APITCH * 4;   // 110592
    const int SMEM64  = STG * (128 + 64) * APITCH * 4;    //  82944
    static bool attr_done = false;
    if (!attr_done) {
        cudaFuncSetAttribute(mma_gemm_nt<128, 0, false, true>,
                             cudaFuncAttributeMaxDynamicSharedMemorySize, SMEM128);
        cudaFuncSetAttribute(mma_gemm_nt<128, 0, false, false>,
                             cudaFuncAttributeMaxDynamicSharedMemorySize, SMEM128);
        cudaFuncSetAttribute(mma_gemm_nt<128, 1, false, false>,
                             cudaFuncAttributeMaxDynamicSharedMemorySize, SMEM128);
        cudaFuncSetAttribute(mma_gemm_nt<128, 2, false, false>,
                             cudaFuncAttributeMaxDynamicSharedMemorySize, SMEM128);
        cudaFuncSetAttribute(mma_gemm_nt<64, 0, true, true>,
                             cudaFuncAttributeMaxDynamicSharedMemorySize, SMEM64);
        attr_done = true;
    }

    const long SS = (long)S * S;

    // 0) round all inputs to tf32 (rna) — single launch
    round_all<<<(RN_TOT + 255) / 256, 256>>>(x, xr, Wqkv, wqkvr, Wout, woutr,
                                             Wpos, wposr, rel, relr);

    // 1) qkv = x @ Wqkv^T
    mma_gemm_nt<128, 0, false, true><<<dim3(24, 16, 1), 256, SMEM128>>>(
        xr, VDIM, 0, wqkvr, VDIM, 0, qkv, 3 * VDIM, 0, VDIM);

    // 2) relproj = rel @ Wpos^T
    mma_gemm_nt<128, 0, false, true><<<dim3(8, 16, 1), 256, SMEM128>>>(
        relr, VDIM, 0, wposr, VDIM, 0, relproj, VDIM, 0, VDIM);

    // 3) qu = q + u, qv = q + v   (tf32-rounded)
    make_quqv<<<(S * VDIM) / 256, 256>>>(qkv, uvec, vvec, qu, qv);

    // 3b) VT[h*64+d][j] = v[j][64h+d]
    transpose_v<<<dim3(S / 32, VDIM / 32), dim3(32, 8)>>>(qkv, vt);

    // 4) AD[h] = qu_h @ k_h^T  (lower-triangular tiles only)  <-- ncu -s 5 lands here
    mma_gemm_nt<128, 1, false, false><<<dim3(136, 1, 16), 256, SMEM128>>>(
        qu, VDIM, DH, qkv + VDIM, 3 * VDIM, DH, AD, S, SS, DH);

    // 5) QP[h] = qv_h @ rel_h^T  (anti-upper tiles only)
    mma_gemm_nt<128, 2, false, false><<<dim3(136, 1, 16), 256, SMEM128>>>(
        qv, VDIM, DH, relproj, VDIM, DH, QP, S, SS, DH);

    // 6) shift + causal softmax (in place, tf32-rounded probs, pruned trip count)
    softmax_shift<<<dim3(S, NH), 256>>>(AD, QP);

    // 7) attn = P @ V  (NT vs VT, K limited per row block)
    mma_gemm_nt<64, 0, true, true><<<dim3(1, 16, 16), 256, SMEM64>>>(
        AD, S, SS, vt, S, (long)DH * S, attn, VDIM, DH, S);

    // 8) out = attn @ Wout^T
    mma_gemm_nt<128, 0, false, false><<<dim3(8, 16, 1), 256, SMEM128>>>(
        attn, VDIM, 0, woutr, VDIM, 0, out, VDIM, 0, VDIM);
}

// round 9
// speedup vs baseline: 3.8357x; 1.3265x over previous
#include <cuda_runtime.h>
#include <cuda_fp16.h>
#include <cstdint>
#include <math.h>

#define S 2048
#define VDIM 1024
#define NH 16
#define DH 64

// ---------------- scratch (device globals) ---------------------------------
__device__ __half g_xh[S * VDIM];
__device__ __half g_wqkvh[3 * VDIM * VDIM];
__device__ __half g_wouth[VDIM * VDIM];
__device__ __half g_wposh[VDIM * VDIM];
__device__ __half g_relh[S * VDIM];
__device__ float  g_qkv[S * 3 * VDIM];          // fp32 qkv projection
__device__ __half g_quh[S * VDIM];
__device__ __half g_qvh[S * VDIM];
__device__ __half g_kh[S * VDIM];
__device__ __half g_relpjh[S * VDIM];
__device__ __half g_vth[VDIM * S];
__device__ float  g_AD[(size_t)NH * S * S];     // content logits (fp32)
__device__ float  g_QP[(size_t)NH * S * S];     // positional logits (fp32)
__device__ __half g_Ph[(size_t)NH * S * S];     // probs (fp16)
__device__ __half g_attnh[S * VDIM];

// ---------------- helpers ---------------------------------------------------
__device__ __forceinline__ uint32_t cvta_smem(const void* p) {
    uint32_t a;
    asm("{ .reg .u64 t; cvta.to.shared.u64 t, %1; cvt.u32.u64 %0, t; }" : "=r"(a) : "l"(p));
    return a;
}
#define CP16(smem_u32, gptr) \
    asm volatile("cp.async.cg.shared.global [%0], [%1], 16;" :: "r"(smem_u32), "l"(gptr) : "memory")
#define CP_COMMIT() asm volatile("cp.async.commit_group;" ::: "memory")

__device__ __forceinline__ void mma_f16_16x8x16(float* c, const uint32_t* a, const uint32_t* b) {
    asm volatile(
        "mma.sync.aligned.m16n8k16.row.col.f32.f16.f16.f32 "
        "{%0,%1,%2,%3}, {%4,%5,%6,%7}, {%8,%9}, {%0,%1,%2,%3};"
        : "+f"(c[0]), "+f"(c[1]), "+f"(c[2]), "+f"(c[3])
        : "r"(a[0]), "r"(a[1]), "r"(a[2]), "r"(a[3]), "r"(b[0]), "r"(b[1]));
}

// ---------------------------------------------------------------------------
// fp16 mma.sync NT GEMM (fp32 accum): C[m,n] = sum_k A[m,k]*B[n,k]
// BM=128, BN in {128,64}, BK=32 (2x m16n8k16), 3-stage cp.async, 256 threads.
// MODE: 0 = full grid; 1 = lower-tri tiles (br>=bc); 2 = anti-upper (br+bc>=15).
// KROW: limit K to BM*(br+1).  OUTH: 0 = fp32 C, 1 = fp16 C.
// ---------------------------------------------------------------------------
#define BKC 32
#define STG 3
#define HP 40                      // smem pitch in halfs (80B; conflict-free)

template <int BN, int MODE, bool KROW, int OUTH>
__global__ __launch_bounds__(256, 1)
void hgemm_nt(const __half* __restrict__ A, int lda, long aStride,
              const __half* __restrict__ B, int ldb, long bStride,
              void* __restrict__ Cv, int ldc, long cStride, int K)
{
    constexpr int BM = 128;
    constexpr int A_STB = BM * HP * 2;           // bytes per A stage (10240)
    constexpr int B_STB = BN * HP * 2;
    extern __shared__ __half smh[];
    __half* As = smh;                            // [STG][BM][HP]
    __half* Bs = smh + STG * BM * HP;
    const uint32_t sA0 = cvta_smem(As);
    const uint32_t sB0 = cvta_smem(Bs);

    int br, bc;
    if (MODE == 0) {
        br = blockIdx.y; bc = blockIdx.x;
    } else {
        int t = blockIdx.x;
        int r = (int)((sqrtf(8.f * (float)t + 1.f) - 1.f) * 0.5f);
        while ((r + 1) * (r + 2) / 2 <= t) r++;
        while (r * (r + 1) / 2 > t) r--;
        int j = t - r * (r + 1) / 2;
        br = r;
        bc = (MODE == 1) ? j : (15 - r + j);
    }
    const int bz = blockIdx.z;
    A += (long)bz * aStride;
    B += (long)bz * bStride;
    const long row0 = (long)br * BM;
    const long col0 = (long)bc * BN;

    int K_run = K;
    if (KROW) { int kl = BM * (br + 1); if (kl < K_run) K_run = kl; }
    const int NC = K_run / BKC;

    const int tid = threadIdx.x;
    const int wid = tid >> 5, lane = tid & 31;
    const int lq = lane >> 2, lr = lane & 3;

    const int wm0 = (BN == 128) ? (wid >> 2) * 64 : (wid >> 1) * 32;
    const int wn0 = (BN == 128) ? (wid & 3) * 32 : (wid & 1) * 32;
    constexpr int MT = (BN == 128) ? 4 : 2;
    constexpr int NT = 4;

    float acc[MT][NT][4];
#pragma unroll
    for (int i = 0; i < MT; i++)
#pragma unroll
        for (int j = 0; j < NT; j++)
#pragma unroll
            for (int q = 0; q < 4; q++) acc[i][j][q] = 0.f;

    auto load_stage = [&](int c) {
        const int s = c % STG;
        const int k0 = c * BKC;
#pragma unroll
        for (int t2 = 0; t2 < 2; t2++) {         // A: 128 rows x 4 chunks of 16B
            int idx = tid + t2 * 256;
            int row = idx >> 2, kc = idx & 3;
            const __half* g = A + (row0 + row) * (long)lda + k0 + kc * 8;
            CP16(sA0 + (uint32_t)(s * A_STB + row * (HP * 2) + kc * 16), g);
        }
#pragma unroll
        for (int t2 = 0; t2 < (BN == 128 ? 2 : 1); t2++) {
            int idx = tid + t2 * 256;
            int row = idx >> 2, kc = idx & 3;
            const __half* g = B + (col0 + row) * (long)ldb + k0 + kc * 8;
            CP16(sB0 + (uint32_t)(s * B_STB + row * (HP * 2) + kc * 16), g);
        }
        CP_COMMIT();
    };

    const int PRO = (NC < STG - 1) ? NC : (STG - 1);
    for (int c = 0; c < PRO; c++) load_stage(c);

    for (int c = 0; c < NC; c++) {
        int n = NC - 1 - c;
        if (n > STG - 2) n = STG - 2;
        if (n == 0) asm volatile("cp.async.wait_group 0;" ::: "memory");
        else        asm volatile("cp.async.wait_group 1;" ::: "memory");
        __syncthreads();
        if (c + STG - 1 < NC) load_stage(c + STG - 1);

        const __half* aS = As + (c % STG) * BM * HP;
        const __half* bS = Bs + (c % STG) * BN * HP;
#pragma unroll
        for (int ks = 0; ks < 2; ks++) {         // 2x m16n8k16 per 32-K chunk
            const int kk = ks * 16;
            uint32_t af[MT][4];
            uint32_t bf[NT][2];
#pragma unroll
            for (int mt = 0; mt < MT; mt++) {
                const int m = wm0 + mt * 16 + lq;
                af[mt][0] = *(const uint32_t*)&aS[m * HP + kk + 2 * lr];
                af[mt][1] = *(const uint32_t*)&aS[(m + 8) * HP + kk + 2 * lr];
                af[mt][2] = *(const uint32_t*)&aS[m * HP + kk + 2 * lr + 8];
                af[mt][3] = *(const uint32_t*)&aS[(m + 8) * HP + kk + 2 * lr + 8];
            }
#pragma unroll
            for (int nt = 0; nt < NT; nt++) {
                const int nn = wn0 + nt * 8 + lq;
                bf[nt][0] = *(const uint32_t*)&bS[nn * HP + kk + 2 * lr];
                bf[nt][1] = *(const uint32_t*)&bS[nn * HP + kk + 2 * lr + 8];
            }
#pragma unroll
            for (int mt = 0; mt < MT; mt++)
#pragma unroll
                for (int nt = 0; nt < NT; nt++)
                    mma_f16_16x8x16(acc[mt][nt], af[mt], bf[nt]);
        }
    }

    // epilogue
#pragma unroll
    for (int mt = 0; mt < MT; mt++) {
        const long r0 = row0 + wm0 + mt * 16 + lq;
#pragma unroll
        for (int nt = 0; nt < NT; nt++) {
            const int cc = (int)col0 + wn0 + nt * 8 + 2 * lr;
            if (OUTH == 0) {
                float* C = (float*)Cv + (long)bz * cStride;
                *(float2*)&C[r0 * ldc + cc] = make_float2(acc[mt][nt][0], acc[mt][nt][1]);
                *(float2*)&C[(r0 + 8) * ldc + cc] = make_float2(acc[mt][nt][2], acc[mt][nt][3]);
            } else {
                __half* C = (__half*)Cv + (long)bz * cStride;
                *(__half2*)&C[r0 * ldc + cc] = __floats2half2_rn(acc[mt][nt][0], acc[mt][nt][1]);
                *(__half2*)&C[(r0 + 8) * ldc + cc] = __floats2half2_rn(acc[mt][nt][2], acc[mt][nt][3]);
            }
        }
    }
}

// ---------------------------------------------------------------------------
// aux kernels
// ---------------------------------------------------------------------------
// single pass converting all 5 fp32 inputs to fp16 (float4 units -> 4 halfs)
#define RN_X   (S * VDIM / 4)
#define RN_WQ  (3 * VDIM * VDIM / 4)
#define RN_WO  (VDIM * VDIM / 4)
#define RN_WP  (VDIM * VDIM / 4)
#define RN_RE  (S * VDIM / 4)
#define RN_TOT (RN_X + RN_WQ + RN_WO + RN_WP + RN_RE)
__global__ __launch_bounds__(256)
void cvt_all(const float* __restrict__ x, __half* __restrict__ xh,
             const float* __restrict__ wq, __half* __restrict__ wqh,
             const float* __restrict__ wo, __half* __restrict__ woh,
             const float* __restrict__ wp, __half* __restrict__ wph,
             const float* __restrict__ re, __half* __restrict__ reh)
{
    int i = blockIdx.x * blockDim.x + threadIdx.x;   // float4 index
    const float* src; __half* dst;
    if (i < RN_X)                       { src = x;  dst = xh; }
    else if ((i -= RN_X) < RN_WQ)       { src = wq; dst = wqh; }
    else if ((i -= RN_WQ) < RN_WO)      { src = wo; dst = woh; }
    else if ((i -= RN_WO) < RN_WP)      { src = wp; dst = wph; }
    else if ((i -= RN_WP) < RN_RE)      { src = re; dst = reh; }
    else return;
    float4 v = ((const float4*)src)[i];
    __half2* d = (__half2*)(dst + (size_t)i * 4);
    d[0] = __floats2half2_rn(v.x, v.y);
    d[1] = __floats2half2_rn(v.z, v.w);
}

// qu = q+u, qv = q+v, kh = k   (all fp16), from fp32 qkv
__global__ void make_quqvk(const float* __restrict__ qkv, const float* __restrict__ u,
                           const float* __restrict__ v, __half* __restrict__ quh,
                           __half* __restrict__ qvh, __half* __restrict__ kh) {
    int i = blockIdx.x * blockDim.x + threadIdx.x;   // over S*VDIM
    int r = i >> 10, c = i & 1023;
    float q = qkv[r * 3072 + c];
    quh[i] = __float2half_rn(q + u[c]);
    qvh[i] = __float2half_rn(q + v[c]);
    kh[i]  = __float2half_rn(qkv[r * 3072 + VDIM + c]);
}

// VT[h*64+d][j] = v[j][64h+d]  (fp16 out)
__global__ void transpose_v(const float* __restrict__ qkv, __half* __restrict__ vt) {
    __shared__ float t[32][33];
    const int j0 = blockIdx.x * 32, c0 = blockIdx.y * 32;
    const int tx = threadIdx.x, ty = threadIdx.y;
#pragma unroll
    for (int k = 0; k < 32; k += 8)
        t[ty + k][tx] = qkv[(long)(j0 + ty + k) * 3072 + 2 * VDIM + c0 + tx];
    __syncthreads();
#pragma unroll
    for (int k = 0; k < 32; k += 8)
        vt[(long)(c0 + ty + k) * S + j0 + tx] = __float2half_rn(t[tx][ty + k]);
}

// fused shift-gather + causal mask + softmax: AD,QP (fp32) -> Ph (fp16).
// Processes ceil((i+1)/256) chunks; zero-fills masked lanes within touched
// chunks, covering the K_run = 128*(br+1) range read by the KROW PV GEMM.
__global__ __launch_bounds__(256)
void softmax_shift(const float* __restrict__ AD, const float* __restrict__ QP,
                   __half* __restrict__ P) {
    const int i = blockIdx.x;
    const int h = blockIdx.y;
    const float* ad = AD + ((long)h * S + i) * S;
    const float* qp = QP + ((long)h * S + i) * S;
    __half* ph = P + ((long)h * S + i) * S;

    const int nT = (i >> 8) + 1;

    __shared__ float red[8];
    const int tid = threadIdx.x;
    const int lane = tid & 31, warp = tid >> 5;

    float buf[8];
    float lmax = -1e30f;
    for (int t = 0; t < nT; t++) {
        const int j = tid + t * 256;
        float v = -1e30f;
        if (j <= i) {
            const int jj = (j - i - 1 + S) & (S - 1);
            v = (ad[j] + qp[jj]) * 0.125f;
        }
        buf[t] = v;
        lmax = fmaxf(lmax, v);
    }
#pragma unroll
    for (int o = 16; o; o >>= 1) lmax = fmaxf(lmax, __shfl_xor_sync(0xffffffffu, lmax, o));
    if (lane == 0) red[warp] = lmax;
    __syncthreads();
    float m = red[0];
#pragma unroll
    for (int w = 1; w < 8; w++) m = fmaxf(m, red[w]);
    __syncthreads();

    float lsum = 0.f;
    for (int t = 0; t < nT; t++) {
        const int j = tid + t * 256;
        float e = (j <= i) ? __expf(buf[t] - m) : 0.f;
        buf[t] = e;
        lsum += e;
    }
#pragma unroll
    for (int o = 16; o; o >>= 1) lsum += __shfl_xor_sync(0xffffffffu, lsum, o);
    if (lane == 0) red[warp] = lsum;
    __syncthreads();
    float sm = 0.f;
#pragma unroll
    for (int w = 0; w < 8; w++) sm += red[w];
    const float inv = 1.f / sm;

    for (int t = 0; t < nT; t++) {
        const int j = tid + t * 256;
        ph[j] = __float2half_rn(buf[t] * inv);
    }
}

// ---------------------------------------------------------------------------
extern "C" void kernel_launch(void* const* d_in, const int* in_sizes, int n_in,
                              void* d_out, int out_size)
{
    const float* x    = (const float*)d_in[0];
    const float* Wqkv = (const float*)d_in[1];
    const float* Wout = (const float*)d_in[2];
    const float* Wpos = (const float*)d_in[3];
    const float* uvec = (const float*)d_in[4];
    const float* vvec = (const float*)d_in[5];
    const float* rel  = (const float*)d_in[6];
    float* out = (float*)d_out;

    __half *xh, *wqkvh, *wouth, *wposh, *relh, *quh, *qvh, *kh, *relpjh, *vth, *Ph, *attnh;
    float *qkv, *AD, *QP;
    cudaGetSymbolAddress((void**)&xh,     g_xh);
    cudaGetSymbolAddress((void**)&wqkvh,  g_wqkvh);
    cudaGetSymbolAddress((void**)&wouth,  g_wouth);
    cudaGetSymbolAddress((void**)&wposh,  g_wposh);
    cudaGetSymbolAddress((void**)&relh,   g_relh);
    cudaGetSymbolAddress((void**)&qkv,    g_qkv);
    cudaGetSymbolAddress((void**)&quh,    g_quh);
    cudaGetSymbolAddress((void**)&qvh,    g_qvh);
    cudaGetSymbolAddress((void**)&kh,     g_kh);
    cudaGetSymbolAddress((void**)&relpjh, g_relpjh);
    cudaGetSymbolAddress((void**)&vth,    g_vth);
    cudaGetSymbolAddress((void**)&AD,     g_AD);
    cudaGetSymbolAddress((void**)&QP,     g_QP);
    cudaGetSymbolAddress((void**)&Ph,     g_Ph);
    cudaGetSymbolAddress((void**)&attnh,  g_attnh);

    const int SMEM128 = STG * (128 + 128) * HP * 2;   // 61440
    const int SMEM64  = STG * (128 + 64) * HP * 2;    // 46080
    static bool attr_done = false;
    if (!attr_done) {
        cudaFuncSetAttribute(hgemm_nt<128, 0, false, 0>,
                             cudaFuncAttributeMaxDynamicSharedMemorySize, SMEM128);
        cudaFuncSetAttribute(hgemm_nt<128, 0, false, 1>,
                             cudaFuncAttributeMaxDynamicSharedMemorySize, SMEM128);
        cudaFuncSetAttribute(hgemm_nt<128, 1, false, 0>,
                             cudaFuncAttributeMaxDynamicSharedMemorySize, SMEM128);
        cudaFuncSetAttribute(hgemm_nt<128, 2, false, 0>,
                             cudaFuncAttributeMaxDynamicSharedMemorySize, SMEM128);
        cudaFuncSetAttribute(hgemm_nt<64, 0, true, 1>,
                             cudaFuncAttributeMaxDynamicSharedMemorySize, SMEM64);
        attr_done = true;
    }

    const long SS = (long)S * S;

    // 1) convert all inputs to fp16 (single launch)
    cvt_all<<<(RN_TOT + 255) / 256, 256>>>(x, xh, Wqkv, wqkvh, Wout, wouth,
                                           Wpos, wposh, rel, relh);

    // 2) qkv = x @ Wqkv^T  (fp32 out)
    hgemm_nt<128, 0, false, 0><<<dim3(24, 16, 1), 256, SMEM128>>>(
        xh, VDIM, 0, wqkvh, VDIM, 0, qkv, 3 * VDIM, 0, VDIM);

    // 3) qu/qv/k fp16
    make_quqvk<<<(S * VDIM) / 256, 256>>>(qkv, uvec, vvec, quh, qvh, kh);

    // 4) AD[h] = qu_h @ k_h^T  (lower-tri tiles; fp32 out)  <-- ncu slot 4
    hgemm_nt<128, 1, false, 0><<<dim3(136, 1, 16), 256, SMEM128>>>(
        quh, VDIM, DH, kh, VDIM, DH, AD, S, SS, DH);

    // 5) relproj = rel @ Wpos^T  (fp16 out)
    hgemm_nt<128, 0, false, 1><<<dim3(8, 16, 1), 256, SMEM128>>>(
        relh, VDIM, 0, wposh, VDIM, 0, relpjh, VDIM, 0, VDIM);

    // 6) VT (fp16)
    transpose_v<<<dim3(S / 32, VDIM / 32), dim3(32, 8)>>>(qkv, vth);

    // 7) QP[h] = qv_h @ rel_h^T  (anti-upper tiles; fp32 out)
    hgemm_nt<128, 2, false, 0><<<dim3(136, 1, 16), 256, SMEM128>>>(
        qvh, VDIM, DH, relpjh, VDIM, DH, QP, S, SS, DH);

    // 8) shift + causal softmax -> fp16 probs
    softmax_shift<<<dim3(S, NH), 256>>>(AD, QP, Ph);

    // 9) attn = P @ V  (KROW-limited; fp16 out)
    hgemm_nt<64, 0, true, 1><<<dim3(1, 16, 16), 256, SMEM64>>>(
        Ph, S, SS, vth, S, (long)DH * S, attnh, VDIM, DH, S);

    // 10) out = attn @ Wout^T  (fp32 out)
    hgemm_nt<128, 0, false, 0><<<dim3(8, 16, 1), 256, SMEM128>>>(
        attnh, VDIM, 0, wouth, VDIM, 0, out, VDIM, 0, VDIM);
}

// round 10
// speedup vs baseline: 5.7474x; 1.4984x over previous
#include <cuda_runtime.h>
#include <cuda_fp16.h>
#include <cstdint>
#include <math.h>

#define S 2048
#define VDIM 1024
#define NH 16
#define DH 64

// ---------------- scratch (device globals) ---------------------------------
__device__ __half g_xh[S * VDIM];
__device__ __half g_wqkvh[3 * VDIM * VDIM];
__device__ __half g_wouth[VDIM * VDIM];
__device__ __half g_wposh[VDIM * VDIM];
__device__ __half g_relh[S * VDIM];
__device__ float  g_qkv[S * 3 * VDIM];          // fp32 qkv projection
__device__ __half g_quh[S * VDIM];
__device__ __half g_qvh[S * VDIM];
__device__ __half g_kh[S * VDIM];
__device__ __half g_relpjh[S * VDIM];
__device__ __half g_vth[VDIM * S];
__device__ float  g_QP[(size_t)NH * S * S];     // positional logits (fp32)
__device__ __half g_attnh[S * VDIM];

// ---------------- helpers ---------------------------------------------------
__device__ __forceinline__ uint32_t cvta_smem(const void* p) {
    uint32_t a;
    asm("{ .reg .u64 t; cvta.to.shared.u64 t, %1; cvt.u32.u64 %0, t; }" : "=r"(a) : "l"(p));
    return a;
}
#define CP16(smem_u32, gptr) \
    asm volatile("cp.async.cg.shared.global [%0], [%1], 16;" :: "r"(smem_u32), "l"(gptr) : "memory")
#define CP_COMMIT() asm volatile("cp.async.commit_group;" ::: "memory")

__device__ __forceinline__ void mma_f16_16x8x16(float* c, const uint32_t* a, const uint32_t* b) {
    asm volatile(
        "mma.sync.aligned.m16n8k16.row.col.f32.f16.f16.f32 "
        "{%0,%1,%2,%3}, {%4,%5,%6,%7}, {%8,%9}, {%0,%1,%2,%3};"
        : "+f"(c[0]), "+f"(c[1]), "+f"(c[2]), "+f"(c[3])
        : "r"(a[0]), "r"(a[1]), "r"(a[2]), "r"(a[3]), "r"(b[0]), "r"(b[1]));
}

// ---------------------------------------------------------------------------
// fp16 mma.sync NT GEMM (fp32 accum): C[m,n] = sum_k A[m,k]*B[n,k]
// BM=128, BN=128, BK=32 (2x m16n8k16), 3-stage cp.async, 256 threads.
// MODE: 0 = full grid; 2 = anti-upper tiles (br+bc>=15).  OUTH: 0 fp32, 1 fp16.
// ---------------------------------------------------------------------------
#define STG 3
#define HP 40                      // smem pitch in halfs (80B; conflict-free)

template <int MODE, int OUTH>
__global__ __launch_bounds__(256, 1)
void hgemm_nt(const __half* __restrict__ A, int lda, long aStride,
              const __half* __restrict__ B, int ldb, long bStride,
              void* __restrict__ Cv, int ldc, long cStride, int K)
{
    constexpr int BM = 128, BN = 128;
    constexpr int A_STB = BM * HP * 2;
    constexpr int B_STB = BN * HP * 2;
    extern __shared__ __half smh[];
    __half* As = smh;
    __half* Bs = smh + STG * BM * HP;
    const uint32_t sA0 = cvta_smem(As);
    const uint32_t sB0 = cvta_smem(Bs);

    int br, bc;
    if (MODE == 0) {
        br = blockIdx.y; bc = blockIdx.x;
    } else {
        int t = blockIdx.x;
        int r = (int)((sqrtf(8.f * (float)t + 1.f) - 1.f) * 0.5f);
        while ((r + 1) * (r + 2) / 2 <= t) r++;
        while (r * (r + 1) / 2 > t) r--;
        int j = t - r * (r + 1) / 2;
        br = r;
        bc = 15 - r + j;
    }
    const int bz = blockIdx.z;
    A += (long)bz * aStride;
    B += (long)bz * bStride;
    const long row0 = (long)br * BM;
    const long col0 = (long)bc * BN;

    const int NC = K / 32;

    const int tid = threadIdx.x;
    const int wid = tid >> 5, lane = tid & 31;
    const int lq = lane >> 2, lr = lane & 3;

    const int wm0 = (wid >> 2) * 64;
    const int wn0 = (wid & 3) * 32;

    float acc[4][4][4];
#pragma unroll
    for (int i = 0; i < 4; i++)
#pragma unroll
        for (int j = 0; j < 4; j++)
#pragma unroll
            for (int q = 0; q < 4; q++) acc[i][j][q] = 0.f;

    auto load_stage = [&](int c) {
        const int s = c % STG;
        const int k0 = c * 32;
#pragma unroll
        for (int t2 = 0; t2 < 2; t2++) {
            int idx = tid + t2 * 256;
            int row = idx >> 2, kc = idx & 3;
            const __half* g = A + (row0 + row) * (long)lda + k0 + kc * 8;
            CP16(sA0 + (uint32_t)(s * A_STB + row * (HP * 2) + kc * 16), g);
        }
#pragma unroll
        for (int t2 = 0; t2 < 2; t2++) {
            int idx = tid + t2 * 256;
            int row = idx >> 2, kc = idx & 3;
            const __half* g = B + (col0 + row) * (long)ldb + k0 + kc * 8;
            CP16(sB0 + (uint32_t)(s * B_STB + row * (HP * 2) + kc * 16), g);
        }
        CP_COMMIT();
    };

    const int PRO = (NC < STG - 1) ? NC : (STG - 1);
    for (int c = 0; c < PRO; c++) load_stage(c);

    for (int c = 0; c < NC; c++) {
        int n = NC - 1 - c;
        if (n > STG - 2) n = STG - 2;
        if (n == 0) asm volatile("cp.async.wait_group 0;" ::: "memory");
        else        asm volatile("cp.async.wait_group 1;" ::: "memory");
        __syncthreads();
        if (c + STG - 1 < NC) load_stage(c + STG - 1);

        const __half* aS = As + (c % STG) * BM * HP;
        const __half* bS = Bs + (c % STG) * BN * HP;
#pragma unroll
        for (int ks = 0; ks < 2; ks++) {
            const int kk = ks * 16;
            uint32_t af[4][4];
            uint32_t bf[4][2];
#pragma unroll
            for (int mt = 0; mt < 4; mt++) {
                const int m = wm0 + mt * 16 + lq;
                af[mt][0] = *(const uint32_t*)&aS[m * HP + kk + 2 * lr];
                af[mt][1] = *(const uint32_t*)&aS[(m + 8) * HP + kk + 2 * lr];
                af[mt][2] = *(const uint32_t*)&aS[m * HP + kk + 2 * lr + 8];
                af[mt][3] = *(const uint32_t*)&aS[(m + 8) * HP + kk + 2 * lr + 8];
            }
#pragma unroll
            for (int nt = 0; nt < 4; nt++) {
                const int nn = wn0 + nt * 8 + lq;
                bf[nt][0] = *(const uint32_t*)&bS[nn * HP + kk + 2 * lr];
                bf[nt][1] = *(const uint32_t*)&bS[nn * HP + kk + 2 * lr + 8];
            }
#pragma unroll
            for (int mt = 0; mt < 4; mt++)
#pragma unroll
                for (int nt = 0; nt < 4; nt++)
                    mma_f16_16x8x16(acc[mt][nt], af[mt], bf[nt]);
        }
    }

#pragma unroll
    for (int mt = 0; mt < 4; mt++) {
        const long r0 = row0 + wm0 + mt * 16 + lq;
#pragma unroll
        for (int nt = 0; nt < 4; nt++) {
            const int cc = (int)col0 + wn0 + nt * 8 + 2 * lr;
            if (OUTH == 0) {
                float* C = (float*)Cv + (long)bz * cStride;
                *(float2*)&C[r0 * ldc + cc] = make_float2(acc[mt][nt][0], acc[mt][nt][1]);
                *(float2*)&C[(r0 + 8) * ldc + cc] = make_float2(acc[mt][nt][2], acc[mt][nt][3]);
            } else {
                __half* C = (__half*)Cv + (long)bz * cStride;
                *(__half2*)&C[r0 * ldc + cc] = __floats2half2_rn(acc[mt][nt][0], acc[mt][nt][1]);
                *(__half2*)&C[(r0 + 8) * ldc + cc] = __floats2half2_rn(acc[mt][nt][2], acc[mt][nt][3]);
            }
        }
    }
}

// ---------------------------------------------------------------------------
// Fused flash attention: S1 = qu@k^T (tensor), + shifted QP (streamed), causal
// online softmax, O = P@V (tensor).  Block = (head, 128-row block), 8 warps x
// 16 rows. Double-buffered cp.async K/V tiles. Output fp16 attnh (merged heads).
// ---------------------------------------------------------------------------
#define KSH 18432   // bytes per K-tile buffer: 128 rows x 72 halfs x 2
#define VSH 17408   // bytes per V-tile buffer: 64 rows x 136 halfs x 2

__global__ __launch_bounds__(256, 1)
void flash_attn(const __half* __restrict__ quh, const __half* __restrict__ kh,
                const __half* __restrict__ vth, const float* __restrict__ QP,
                __half* __restrict__ attnh)
{
    extern __shared__ __half sm[];
    __half* qs = sm;                           // [128][72]
    __half* ks = sm + 128 * 72;                // [2][128][72]
    __half* vs = sm + 3 * 128 * 72;            // [2][64][136]
    const uint32_t qsA = cvta_smem(qs);
    const uint32_t ksA = cvta_smem(ks);
    const uint32_t vsA = cvta_smem(vs);

    const int br = 15 - (int)(blockIdx.x >> 4);   // big row blocks first
    const int h  = blockIdx.x & 15;
    const int i0 = br * 128;

    const int tid = threadIdx.x;
    const int w = tid >> 5, lane = tid & 31;
    const int lq = lane >> 2, lr = lane & 3;
    const int r0g = i0 + w * 16 + lq;
    const int r1g = r0g + 8;

    auto load_kv = [&](int jt, int buf) {
        const int j0 = jt * 128;
#pragma unroll
        for (int t = 0; t < 4; t++) {
            int idx = tid + t * 256;
            int row = idx >> 3, ch = idx & 7;
            const __half* g = kh + (long)(j0 + row) * VDIM + h * DH + ch * 8;
            CP16(ksA + (uint32_t)(buf * KSH + row * 144 + ch * 16), g);
        }
#pragma unroll
        for (int t = 0; t < 4; t++) {
            int idx = tid + t * 256;
            int row = idx >> 4, ch = idx & 15;
            const __half* g = vth + (long)(h * DH + row) * S + j0 + ch * 8;
            CP16(vsA + (uint32_t)(buf * VSH + row * 272 + ch * 16), g);
        }
        CP_COMMIT();
    };

    // prologue: qu tile + KV tile 0
#pragma unroll
    for (int t = 0; t < 4; t++) {
        int idx = tid + t * 256;
        int row = idx >> 3, ch = idx & 7;
        const __half* g = quh + (long)(i0 + row) * VDIM + h * DH + ch * 8;
        CP16(qsA + (uint32_t)(row * 144 + ch * 16), g);
    }
    CP_COMMIT();
    load_kv(0, 0);
    asm volatile("cp.async.wait_group 0;" ::: "memory");
    __syncthreads();

    uint32_t quA[4][4];
#pragma unroll
    for (int kc = 0; kc < 4; kc++) {
        quA[kc][0] = *(const uint32_t*)&qs[(w * 16 + lq) * 72 + kc * 16 + 2 * lr];
        quA[kc][1] = *(const uint32_t*)&qs[(w * 16 + lq + 8) * 72 + kc * 16 + 2 * lr];
        quA[kc][2] = *(const uint32_t*)&qs[(w * 16 + lq) * 72 + kc * 16 + 2 * lr + 8];
        quA[kc][3] = *(const uint32_t*)&qs[(w * 16 + lq + 8) * 72 + kc * 16 + 2 * lr + 8];
    }

    float O[8][4];
#pragma unroll
    for (int i = 0; i < 8; i++)
#pragma unroll
        for (int q = 0; q < 4; q++) O[i][q] = 0.f;
    float m0 = -1e30f, m1 = -1e30f, l0 = 0.f, l1 = 0.f;

    const float* qp0 = QP + ((long)h * S + r0g) * S;
    const float* qp1 = qp0 + 8 * S;

    for (int jt = 0; jt <= br; jt++) {
        if (jt < br) {
            load_kv(jt + 1, (jt + 1) & 1);
            asm volatile("cp.async.wait_group 1;" ::: "memory");
        } else {
            asm volatile("cp.async.wait_group 0;" ::: "memory");
        }
        __syncthreads();

        const __half* ksb = ks + (jt & 1) * (128 * 72);
        const __half* vsb = vs + (jt & 1) * (64 * 136);
        const int j0 = jt * 128;

        float s[16][4];
#pragma unroll
        for (int i = 0; i < 16; i++)
#pragma unroll
            for (int q = 0; q < 4; q++) s[i][q] = 0.f;

        // S1 = qu @ k^T
#pragma unroll
        for (int kc = 0; kc < 4; kc++)
#pragma unroll
            for (int nt = 0; nt < 16; nt++) {
                uint32_t bb[2];
                bb[0] = *(const uint32_t*)&ksb[(nt * 8 + lq) * 72 + kc * 16 + 2 * lr];
                bb[1] = *(const uint32_t*)&ksb[(nt * 8 + lq) * 72 + kc * 16 + 2 * lr + 8];
                mma_f16_16x8x16(s[nt], quA[kc], bb);
            }

        // + shifted QP, scale
        {
            const int b0 = j0 - r0g - 1 + 2 * S;
            const int b1 = b0 - 8;
#pragma unroll
            for (int nt = 0; nt < 16; nt++) {
                const int jA = nt * 8 + 2 * lr;
                s[nt][0] = (s[nt][0] + qp0[(b0 + jA) & (S - 1)]) * 0.125f;
                s[nt][1] = (s[nt][1] + qp0[(b0 + jA + 1) & (S - 1)]) * 0.125f;
                s[nt][2] = (s[nt][2] + qp1[(b1 + jA) & (S - 1)]) * 0.125f;
                s[nt][3] = (s[nt][3] + qp1[(b1 + jA + 1) & (S - 1)]) * 0.125f;
            }
        }
        // causal mask (diagonal tile only)
        if (jt == br) {
#pragma unroll
            for (int nt = 0; nt < 16; nt++) {
                const int j = j0 + nt * 8 + 2 * lr;
                if (j > r0g)     s[nt][0] = -1e30f;
                if (j + 1 > r0g) s[nt][1] = -1e30f;
                if (j > r1g)     s[nt][2] = -1e30f;
                if (j + 1 > r1g) s[nt][3] = -1e30f;
            }
        }

        // online softmax
        float mx0 = -1e30f, mx1 = -1e30f;
#pragma unroll
        for (int nt = 0; nt < 16; nt++) {
            mx0 = fmaxf(mx0, fmaxf(s[nt][0], s[nt][1]));
            mx1 = fmaxf(mx1, fmaxf(s[nt][2], s[nt][3]));
        }
        mx0 = fmaxf(mx0, __shfl_xor_sync(0xffffffffu, mx0, 1));
        mx0 = fmaxf(mx0, __shfl_xor_sync(0xffffffffu, mx0, 2));
        mx1 = fmaxf(mx1, __shfl_xor_sync(0xffffffffu, mx1, 1));
        mx1 = fmaxf(mx1, __shfl_xor_sync(0xffffffffu, mx1, 2));
        const float m0n = fmaxf(m0, mx0), m1n = fmaxf(m1, mx1);
        const float sc0 = __expf(m0 - m0n), sc1 = __expf(m1 - m1n);
        m0 = m0n; m1 = m1n;

        uint32_t pa[8][4];
        float rs0 = 0.f, rs1 = 0.f;
#pragma unroll
        for (int kc = 0; kc < 8; kc++) {
            float p00 = __expf(s[2 * kc][0] - m0),     p01 = __expf(s[2 * kc][1] - m0);
            float p02 = __expf(s[2 * kc][2] - m1),     p03 = __expf(s[2 * kc][3] - m1);
            float p10 = __expf(s[2 * kc + 1][0] - m0), p11 = __expf(s[2 * kc + 1][1] - m0);
            float p12 = __expf(s[2 * kc + 1][2] - m1), p13 = __expf(s[2 * kc + 1][3] - m1);
            rs0 += p00 + p01 + p10 + p11;
            rs1 += p02 + p03 + p12 + p13;
            *(__half2*)&pa[kc][0] = __floats2half2_rn(p00, p01);
            *(__half2*)&pa[kc][1] = __floats2half2_rn(p02, p03);
            *(__half2*)&pa[kc][2] = __floats2half2_rn(p10, p11);
            *(__half2*)&pa[kc][3] = __floats2half2_rn(p12, p13);
        }
        rs0 += __shfl_xor_sync(0xffffffffu, rs0, 1);
        rs0 += __shfl_xor_sync(0xffffffffu, rs0, 2);
        rs1 += __shfl_xor_sync(0xffffffffu, rs1, 1);
        rs1 += __shfl_xor_sync(0xffffffffu, rs1, 2);
        l0 = l0 * sc0 + rs0;
        l1 = l1 * sc1 + rs1;
#pragma unroll
        for (int nt = 0; nt < 8; nt++) {
            O[nt][0] *= sc0; O[nt][1] *= sc0;
            O[nt][2] *= sc1; O[nt][3] *= sc1;
        }

        // O += P @ V
#pragma unroll
        for (int kc = 0; kc < 8; kc++)
#pragma unroll
            for (int nt = 0; nt < 8; nt++) {
                uint32_t bb[2];
                bb[0] = *(const uint32_t*)&vsb[(nt * 8 + lq) * 136 + kc * 16 + 2 * lr];
                bb[1] = *(const uint32_t*)&vsb[(nt * 8 + lq) * 136 + kc * 16 + 2 * lr + 8];
                mma_f16_16x8x16(O[nt], pa[kc], bb);
            }
        __syncthreads();
    }

    // epilogue
    const float il0 = 1.f / l0, il1 = 1.f / l1;
#pragma unroll
    for (int nt = 0; nt < 8; nt++) {
        const int cc = h * DH + nt * 8 + 2 * lr;
        *(__half2*)&attnh[(long)r0g * VDIM + cc] =
            __floats2half2_rn(O[nt][0] * il0, O[nt][1] * il0);
        *(__half2*)&attnh[(long)r1g * VDIM + cc] =
            __floats2half2_rn(O[nt][2] * il1, O[nt][3] * il1);
    }
}

// ---------------------------------------------------------------------------
// aux kernels
// ---------------------------------------------------------------------------
#define RN_X   (S * VDIM / 4)
#define RN_WQ  (3 * VDIM * VDIM / 4)
#define RN_WO  (VDIM * VDIM / 4)
#define RN_WP  (VDIM * VDIM / 4)
#define RN_RE  (S * VDIM / 4)
#define RN_TOT (RN_X + RN_WQ + RN_WO + RN_WP + RN_RE)
__global__ __launch_bounds__(256)
void cvt_all(const float* __restrict__ x, __half* __restrict__ xh,
             const float* __restrict__ wq, __half* __restrict__ wqh,
             const float* __restrict__ wo, __half* __restrict__ woh,
             const float* __restrict__ wp, __half* __restrict__ wph,
             const float* __restrict__ re, __half* __restrict__ reh)
{
    int i = blockIdx.x * blockDim.x + threadIdx.x;
    const float* src; __half* dst;
    if (i < RN_X)                       { src = x;  dst = xh; }
    else if ((i -= RN_X) < RN_WQ)       { src = wq; dst = wqh; }
    else if ((i -= RN_WQ) < RN_WO)      { src = wo; dst = woh; }
    else if ((i -= RN_WO) < RN_WP)      { src = wp; dst = wph; }
    else if ((i -= RN_WP) < RN_RE)      { src = re; dst = reh; }
    else return;
    float4 v = ((const float4*)src)[i];
    __half2* d = (__half2*)(dst + (size_t)i * 4);
    d[0] = __floats2half2_rn(v.x, v.y);
    d[1] = __floats2half2_rn(v.z, v.w);
}

__global__ void make_quqvk(const float* __restrict__ qkv, const float* __restrict__ u,
                           const float* __restrict__ v, __half* __restrict__ quh,
                           __half* __restrict__ qvh, __half* __restrict__ kh) {
    int i = blockIdx.x * blockDim.x + threadIdx.x;
    int r = i >> 10, c = i & 1023;
    float q = qkv[r * 3072 + c];
    quh[i] = __float2half_rn(q + u[c]);
    qvh[i] = __float2half_rn(q + v[c]);
    kh[i]  = __float2half_rn(qkv[r * 3072 + VDIM + c]);
}

__global__ void transpose_v(const float* __restrict__ qkv, __half* __restrict__ vt) {
    __shared__ float t[32][33];
    const int j0 = blockIdx.x * 32, c0 = blockIdx.y * 32;
    const int tx = threadIdx.x, ty = threadIdx.y;
#pragma unroll
    for (int k = 0; k < 32; k += 8)
        t[ty + k][tx] = qkv[(long)(j0 + ty + k) * 3072 + 2 * VDIM + c0 + tx];
    __syncthreads();
#pragma unroll
    for (int k = 0; k < 32; k += 8)
        vt[(long)(c0 + ty + k) * S + j0 + tx] = __float2half_rn(t[tx][ty + k]);
}

// ---------------------------------------------------------------------------
extern "C" void kernel_launch(void* const* d_in, const int* in_sizes, int n_in,
                              void* d_out, int out_size)
{
    const float* x    = (const float*)d_in[0];
    const float* Wqkv = (const float*)d_in[1];
    const float* Wout = (const float*)d_in[2];
    const float* Wpos = (const float*)d_in[3];
    const float* uvec = (const float*)d_in[4];
    const float* vvec = (const float*)d_in[5];
    const float* rel  = (const float*)d_in[6];
    float* out = (float*)d_out;

    __half *xh, *wqkvh, *wouth, *wposh, *relh, *quh, *qvh, *kh, *relpjh, *vth, *attnh;
    float *qkv, *QP;
    cudaGetSymbolAddress((void**)&xh,     g_xh);
    cudaGetSymbolAddress((void**)&wqkvh,  g_wqkvh);
    cudaGetSymbolAddress((void**)&wouth,  g_wouth);
    cudaGetSymbolAddress((void**)&wposh,  g_wposh);
    cudaGetSymbolAddress((void**)&relh,   g_relh);
    cudaGetSymbolAddress((void**)&qkv,    g_qkv);
    cudaGetSymbolAddress((void**)&quh,    g_quh);
    cudaGetSymbolAddress((void**)&qvh,    g_qvh);
    cudaGetSymbolAddress((void**)&kh,     g_kh);
    cudaGetSymbolAddress((void**)&relpjh, g_relpjh);
    cudaGetSymbolAddress((void**)&vth,    g_vth);
    cudaGetSymbolAddress((void**)&QP,     g_QP);
    cudaGetSymbolAddress((void**)&attnh,  g_attnh);

    const int SMEMG = STG * (128 + 128) * HP * 2;        // 61440
    const int SMEMF = (3 * 128 * 72 + 2 * 64 * 136) * 2; // 90112
    static bool attr_done = false;
    if (!attr_done) {
        cudaFuncSetAttribute(hgemm_nt<0, 0>, cudaFuncAttributeMaxDynamicSharedMemorySize, SMEMG);
        cudaFuncSetAttribute(hgemm_nt<0, 1>, cudaFuncAttributeMaxDynamicSharedMemorySize, SMEMG);
        cudaFuncSetAttribute(hgemm_nt<2, 0>, cudaFuncAttributeMaxDynamicSharedMemorySize, SMEMG);
        cudaFuncSetAttribute(flash_attn, cudaFuncAttributeMaxDynamicSharedMemorySize, SMEMF);
        attr_done = true;
    }

    const long SS = (long)S * S;

    // 1) convert all inputs to fp16
    cvt_all<<<(RN_TOT + 255) / 256, 256>>>(x, xh, Wqkv, wqkvh, Wout, wouth,
                                           Wpos, wposh, rel, relh);

    // 2) qkv = x @ Wqkv^T  (fp32 out)
    hgemm_nt<0, 0><<<dim3(24, 16, 1), 256, SMEMG>>>(
        xh, VDIM, 0, wqkvh, VDIM, 0, qkv, 3 * VDIM, 0, VDIM);

    // 3) qu/qv/k fp16
    make_quqvk<<<(S * VDIM) / 256, 256>>>(qkv, uvec, vvec, quh, qvh, kh);

    // 4) relproj = rel @ Wpos^T  (fp16 out)
    hgemm_nt<0, 1><<<dim3(8, 16, 1), 256, SMEMG>>>(
        relh, VDIM, 0, wposh, VDIM, 0, relpjh, VDIM, 0, VDIM);

    // 5) VT (fp16)
    transpose_v<<<dim3(S / 32, VDIM / 32), dim3(32, 8)>>>(qkv, vth);

    // 6) QP[h] = qv_h @ rel_h^T  (anti-upper tiles; fp32 out)
    hgemm_nt<2, 0><<<dim3(136, 1, 16), 256, SMEMG>>>(
        qvh, VDIM, DH, relpjh, VDIM, DH, QP, S, SS, DH);

    // 7) fused flash attention (qu·k^T + shift-QP + softmax + P·V)
    flash_attn<<<dim3(256), 256, SMEMF>>>(quh, kh, vth, QP, attnh);

    // 8) out = attn @ Wout^T  (fp32 out)
    hgemm_nt<0, 0><<<dim3(8, 16, 1), 256, SMEMG>>>(
        attnh, VDIM, 0, wouth, VDIM, 0, out, VDIM, 0, VDIM);
}

// round 12
// speedup vs baseline: 6.5316x; 1.1364x over previous
#include <cuda_runtime.h>
#include <cuda_fp16.h>
#include <cstdint>
#include <math.h>

#define S 2048
#define VDIM 1024
#define NH 16
#define DH 64

// ---------------- scratch (device globals) ---------------------------------
__device__ __half g_xh[S * VDIM];
__device__ __half g_wqkvh[3 * VDIM * VDIM];
__device__ __half g_wouth[VDIM * VDIM];
__device__ __half g_wposh[VDIM * VDIM];
__device__ __half g_relh[S * VDIM];
__device__ __half g_quh[S * VDIM];
__device__ __half g_qvh[S * VDIM];
__device__ __half g_kh[S * VDIM];
__device__ __half g_relpjh[S * VDIM];
__device__ __half g_vth[VDIM * S];
__device__ float  g_QP[(size_t)NH * S * S];     // positional logits (fp32)
__device__ __half g_attnh[S * VDIM];

// ---------------- helpers ---------------------------------------------------
__device__ __forceinline__ uint32_t cvta_smem(const void* p) {
    uint32_t a;
    asm("{ .reg .u64 t; cvta.to.shared.u64 t, %1; cvt.u32.u64 %0, t; }" : "=r"(a) : "l"(p));
    return a;
}
#define CP16(smem_u32, gptr) \
    asm volatile("cp.async.cg.shared.global [%0], [%1], 16;" :: "r"(smem_u32), "l"(gptr) : "memory")
#define CP_COMMIT() asm volatile("cp.async.commit_group;" ::: "memory")

__device__ __forceinline__ void mma_f16_16x8x16(float* c, const uint32_t* a, const uint32_t* b) {
    asm volatile(
        "mma.sync.aligned.m16n8k16.row.col.f32.f16.f16.f32 "
        "{%0,%1,%2,%3}, {%4,%5,%6,%7}, {%8,%9}, {%0,%1,%2,%3};"
        : "+f"(c[0]), "+f"(c[1]), "+f"(c[2]), "+f"(c[3])
        : "r"(a[0]), "r"(a[1]), "r"(a[2]), "r"(a[3]), "r"(b[0]), "r"(b[1]));
}

#define STG 3
#define HP 40                      // smem pitch in halfs (80B; conflict-free)

// ---------------------------------------------------------------------------
// fp16 NT GEMM, BM=BN=128, BK=32, 3-stage cp.async, 256 threads, 2 CTAs/SM.
// MODE: 0 = full grid; 2 = anti-upper tiles (br+bc>=15).  OUTH: 0 fp32, 1 fp16.
// ---------------------------------------------------------------------------
template <int MODE, int OUTH>
__global__ __launch_bounds__(256, 2)
void hgemm_nt(const __half* __restrict__ A, int lda, long aStride,
              const __half* __restrict__ B, int ldb, long bStride,
              void* __restrict__ Cv, int ldc, long cStride, int K)
{
    constexpr int BM = 128, BN = 128;
    constexpr int A_STB = BM * HP * 2;
    constexpr int B_STB = BN * HP * 2;
    extern __shared__ __half smh[];
    __half* As = smh;
    __half* Bs = smh + STG * BM * HP;
    const uint32_t sA0 = cvta_smem(As);
    const uint32_t sB0 = cvta_smem(Bs);

    int br, bc;
    if (MODE == 0) {
        br = blockIdx.y; bc = blockIdx.x;
    } else {            // anti-upper tiles: br+bc>=15
        int t = blockIdx.x;
        int r = (int)((sqrtf(8.f * (float)t + 1.f) - 1.f) * 0.5f);
        while ((r + 1) * (r + 2) / 2 <= t) r++;
        while (r * (r + 1) / 2 > t) r--;
        int j = t - r * (r + 1) / 2;
        br = r;
        bc = 15 - r + j;
    }
    const int bz = blockIdx.z;
    A += (long)bz * aStride;
    B += (long)bz * bStride;
    const long row0 = (long)br * BM;
    const long col0 = (long)bc * BN;

    const int NC = K / 32;

    const int tid = threadIdx.x;
    const int wid = tid >> 5, lane = tid & 31;
    const int lq = lane >> 2, lr = lane & 3;
    const int wm0 = (wid >> 2) * 64;
    const int wn0 = (wid & 3) * 32;

    float acc[4][4][4];
#pragma unroll
    for (int i = 0; i < 4; i++)
#pragma unroll
        for (int j = 0; j < 4; j++)
#pragma unroll
            for (int q = 0; q < 4; q++) acc[i][j][q] = 0.f;

    auto load_stage = [&](int c) {
        const int s = c % STG;
        const int k0 = c * 32;
#pragma unroll
        for (int t2 = 0; t2 < 2; t2++) {
            int idx = tid + t2 * 256;
            int row = idx >> 2, kc = idx & 3;
            const __half* g = A + (row0 + row) * (long)lda + k0 + kc * 8;
            CP16(sA0 + (uint32_t)(s * A_STB + row * (HP * 2) + kc * 16), g);
        }
#pragma unroll
        for (int t2 = 0; t2 < 2; t2++) {
            int idx = tid + t2 * 256;
            int row = idx >> 2, kc = idx & 3;
            const __half* g = B + (col0 + row) * (long)ldb + k0 + kc * 8;
            CP16(sB0 + (uint32_t)(s * B_STB + row * (HP * 2) + kc * 16), g);
        }
        CP_COMMIT();
    };

    const int PRO = (NC < STG - 1) ? NC : (STG - 1);
    for (int c = 0; c < PRO; c++) load_stage(c);

    for (int c = 0; c < NC; c++) {
        int n = NC - 1 - c;
        if (n > STG - 2) n = STG - 2;
        if (n == 0) asm volatile("cp.async.wait_group 0;" ::: "memory");
        else        asm volatile("cp.async.wait_group 1;" ::: "memory");
        __syncthreads();
        if (c + STG - 1 < NC) load_stage(c + STG - 1);

        const __half* aS = As + (c % STG) * BM * HP;
        const __half* bS = Bs + (c % STG) * BN * HP;
#pragma unroll
        for (int ks = 0; ks < 2; ks++) {
            const int kk = ks * 16;
            uint32_t af[4][4];
            uint32_t bf[4][2];
#pragma unroll
            for (int mt = 0; mt < 4; mt++) {
                const int m = wm0 + mt * 16 + lq;
                af[mt][0] = *(const uint32_t*)&aS[m * HP + kk + 2 * lr];
                af[mt][1] = *(const uint32_t*)&aS[(m + 8) * HP + kk + 2 * lr];
                af[mt][2] = *(const uint32_t*)&aS[m * HP + kk + 2 * lr + 8];
                af[mt][3] = *(const uint32_t*)&aS[(m + 8) * HP + kk + 2 * lr + 8];
            }
#pragma unroll
            for (int nt = 0; nt < 4; nt++) {
                const int nn = wn0 + nt * 8 + lq;
                bf[nt][0] = *(const uint32_t*)&bS[nn * HP + kk + 2 * lr];
                bf[nt][1] = *(const uint32_t*)&bS[nn * HP + kk + 2 * lr + 8];
            }
#pragma unroll
            for (int mt = 0; mt < 4; mt++)
#pragma unroll
                for (int nt = 0; nt < 4; nt++)
                    mma_f16_16x8x16(acc[mt][nt], af[mt], bf[nt]);
        }
    }

#pragma unroll
    for (int mt = 0; mt < 4; mt++) {
        const long r0 = row0 + wm0 + mt * 16 + lq;
#pragma unroll
        for (int nt = 0; nt < 4; nt++) {
            const int cc = (int)col0 + wn0 + nt * 8 + 2 * lr;
            if (OUTH == 0) {
                float* C = (float*)Cv + (long)bz * cStride;
                *(float2*)&C[r0 * ldc + cc] = make_float2(acc[mt][nt][0], acc[mt][nt][1]);
                *(float2*)&C[(r0 + 8) * ldc + cc] = make_float2(acc[mt][nt][2], acc[mt][nt][3]);
            } else {
                __half* C = (__half*)Cv + (long)bz * cStride;
                *(__half2*)&C[r0 * ldc + cc] = __floats2half2_rn(acc[mt][nt][0], acc[mt][nt][1]);
                *(__half2*)&C[(r0 + 8) * ldc + cc] = __floats2half2_rn(acc[mt][nt][2], acc[mt][nt][3]);
            }
        }
    }
}

// ---------------------------------------------------------------------------
// qkv GEMM with fused epilogue: writes quh=q+u, qvh=q+v, kh, and transposed
// vth directly. Grid (24,16): bx 0-7 q-cols, 8-15 k-cols, 16-23 v-cols.
// ---------------------------------------------------------------------------
__global__ __launch_bounds__(256, 2)
void hgemm_qkv(const __half* __restrict__ A, const __half* __restrict__ B,
               const float* __restrict__ uvec, const float* __restrict__ vvec,
               __half* __restrict__ quh, __half* __restrict__ qvh,
               __half* __restrict__ kh, __half* __restrict__ vth)
{
    constexpr int BM = 128, BN = 128;
    constexpr int A_STB = BM * HP * 2;
    constexpr int B_STB = BN * HP * 2;
    extern __shared__ __half smh[];
    __half* As = smh;
    __half* Bs = smh + STG * BM * HP;
    const uint32_t sA0 = cvta_smem(As);
    const uint32_t sB0 = cvta_smem(Bs);

    const int br = blockIdx.y, bc = blockIdx.x;
    const long row0 = (long)br * BM;
    const long col0 = (long)bc * BN;
    const int NC = VDIM / 32;

    const int tid = threadIdx.x;
    const int wid = tid >> 5, lane = tid & 31;
    const int lq = lane >> 2, lr = lane & 3;
    const int wm0 = (wid >> 2) * 64;
    const int wn0 = (wid & 3) * 32;

    float acc[4][4][4];
#pragma unroll
    for (int i = 0; i < 4; i++)
#pragma unroll
        for (int j = 0; j < 4; j++)
#pragma unroll
            for (int q = 0; q < 4; q++) acc[i][j][q] = 0.f;

    auto load_stage = [&](int c) {
        const int s = c % STG;
        const int k0 = c * 32;
#pragma unroll
        for (int t2 = 0; t2 < 2; t2++) {
            int idx = tid + t2 * 256;
            int row = idx >> 2, kc = idx & 3;
            const __half* g = A + (row0 + row) * (long)VDIM + k0 + kc * 8;
            CP16(sA0 + (uint32_t)(s * A_STB + row * (HP * 2) + kc * 16), g);
        }
#pragma unroll
        for (int t2 = 0; t2 < 2; t2++) {
            int idx = tid + t2 * 256;
            int row = idx >> 2, kc = idx & 3;
            const __half* g = B + (col0 + row) * (long)VDIM + k0 + kc * 8;
            CP16(sB0 + (uint32_t)(s * B_STB + row * (HP * 2) + kc * 16), g);
        }
        CP_COMMIT();
    };

    for (int c = 0; c < STG - 1; c++) load_stage(c);

    for (int c = 0; c < NC; c++) {
        int n = NC - 1 - c;
        if (n > STG - 2) n = STG - 2;
        if (n == 0) asm volatile("cp.async.wait_group 0;" ::: "memory");
        else        asm volatile("cp.async.wait_group 1;" ::: "memory");
        __syncthreads();
        if (c + STG - 1 < NC) load_stage(c + STG - 1);

        const __half* aS = As + (c % STG) * BM * HP;
        const __half* bS = Bs + (c % STG) * BN * HP;
#pragma unroll
        for (int ks = 0; ks < 2; ks++) {
            const int kk = ks * 16;
            uint32_t af[4][4];
            uint32_t bf[4][2];
#pragma unroll
            for (int mt = 0; mt < 4; mt++) {
                const int m = wm0 + mt * 16 + lq;
                af[mt][0] = *(const uint32_t*)&aS[m * HP + kk + 2 * lr];
                af[mt][1] = *(const uint32_t*)&aS[(m + 8) * HP + kk + 2 * lr];
                af[mt][2] = *(const uint32_t*)&aS[m * HP + kk + 2 * lr + 8];
                af[mt][3] = *(const uint32_t*)&aS[(m + 8) * HP + kk + 2 * lr + 8];
            }
#pragma unroll
            for (int nt = 0; nt < 4; nt++) {
                const int nn = wn0 + nt * 8 + lq;
                bf[nt][0] = *(const uint32_t*)&bS[nn * HP + kk + 2 * lr];
                bf[nt][1] = *(const uint32_t*)&bS[nn * HP + kk + 2 * lr + 8];
            }
#pragma unroll
            for (int mt = 0; mt < 4; mt++)
#pragma unroll
                for (int nt = 0; nt < 4; nt++)
                    mma_f16_16x8x16(acc[mt][nt], af[mt], bf[nt]);
        }
    }

    const int type = bc >> 3;                 // 0=q, 1=k, 2=v
    const int colq0 = (int)col0 - (type << 10);

    if (type == 2) {
        // transpose through smem, then write vth[vcol][seq]
        __syncthreads();
        __half* tb = smh;                     // [128 cols][136 pitch] (seq inner)
#pragma unroll
        for (int mt = 0; mt < 4; mt++) {
            const int r = wm0 + mt * 16 + lq;
#pragma unroll
            for (int nt = 0; nt < 4; nt++) {
                const int cc = wn0 + nt * 8 + 2 * lr;
                tb[cc * 136 + r]           = __float2half_rn(acc[mt][nt][0]);
                tb[(cc + 1) * 136 + r]     = __float2half_rn(acc[mt][nt][1]);
                tb[cc * 136 + r + 8]       = __float2half_rn(acc[mt][nt][2]);
                tb[(cc + 1) * 136 + r + 8] = __float2half_rn(acc[mt][nt][3]);
            }
        }
        __syncthreads();
        // FIX (R11 bug): full coverage needs 128 cols x 16 chunks of 8 halfs.
#pragma unroll
        for (int t = 0; t < 8; t++) {
            int idx = tid + t * 256;
            int c = idx >> 4, ch = idx & 15;   // c: local v-col, ch: 16B chunk
            *(float4*)&vth[(long)(colq0 + c) * S + row0 + ch * 8] =
                *(const float4*)&tb[c * 136 + ch * 8];
        }
    } else {
#pragma unroll
        for (int mt = 0; mt < 4; mt++) {
            const long r0 = row0 + wm0 + mt * 16 + lq;
#pragma unroll
            for (int nt = 0; nt < 4; nt++) {
                const int cc = colq0 + wn0 + nt * 8 + 2 * lr;
                if (type == 0) {
                    const float u0 = uvec[cc], u1 = uvec[cc + 1];
                    const float v0 = vvec[cc], v1 = vvec[cc + 1];
                    *(__half2*)&quh[r0 * VDIM + cc] =
                        __floats2half2_rn(acc[mt][nt][0] + u0, acc[mt][nt][1] + u1);
                    *(__half2*)&quh[(r0 + 8) * VDIM + cc] =
                        __floats2half2_rn(acc[mt][nt][2] + u0, acc[mt][nt][3] + u1);
                    *(__half2*)&qvh[r0 * VDIM + cc] =
                        __floats2half2_rn(acc[mt][nt][0] + v0, acc[mt][nt][1] + v1);
                    *(__half2*)&qvh[(r0 + 8) * VDIM + cc] =
                        __floats2half2_rn(acc[mt][nt][2] + v0, acc[mt][nt][3] + v1);
                } else {
                    *(__half2*)&kh[r0 * VDIM + cc] =
                        __floats2half2_rn(acc[mt][nt][0], acc[mt][nt][1]);
                    *(__half2*)&kh[(r0 + 8) * VDIM + cc] =
                        __floats2half2_rn(acc[mt][nt][2], acc[mt][nt][3]);
                }
            }
        }
    }
}

// ---------------------------------------------------------------------------
// Fused flash attention
// ---------------------------------------------------------------------------
#define KSH 18432
#define VSH 17408

__global__ __launch_bounds__(256, 1)
void flash_attn(const __half* __restrict__ quh, const __half* __restrict__ kh,
                const __half* __restrict__ vth, const float* __restrict__ QP,
                __half* __restrict__ attnh)
{
    extern __shared__ __half sm[];
    __half* qs = sm;
    __half* ks = sm + 128 * 72;
    __half* vs = sm + 3 * 128 * 72;
    const uint32_t qsA = cvta_smem(qs);
    const uint32_t ksA = cvta_smem(ks);
    const uint32_t vsA = cvta_smem(vs);

    const int br = 15 - (int)(blockIdx.x >> 4);
    const int h  = blockIdx.x & 15;
    const int i0 = br * 128;

    const int tid = threadIdx.x;
    const int w = tid >> 5, lane = tid & 31;
    const int lq = lane >> 2, lr = lane & 3;
    const int r0g = i0 + w * 16 + lq;
    const int r1g = r0g + 8;

    auto load_kv = [&](int jt, int buf) {
        const int j0 = jt * 128;
#pragma unroll
        for (int t = 0; t < 4; t++) {
            int idx = tid + t * 256;
            int row = idx >> 3, ch = idx & 7;
            const __half* g = kh + (long)(j0 + row) * VDIM + h * DH + ch * 8;
            CP16(ksA + (uint32_t)(buf * KSH + row * 144 + ch * 16), g);
        }
#pragma unroll
        for (int t = 0; t < 4; t++) {
            int idx = tid + t * 256;
            int row = idx >> 4, ch = idx & 15;
            const __half* g = vth + (long)(h * DH + row) * S + j0 + ch * 8;
            CP16(vsA + (uint32_t)(buf * VSH + row * 272 + ch * 16), g);
        }
        CP_COMMIT();
    };

#pragma unroll
    for (int t = 0; t < 4; t++) {
        int idx = tid + t * 256;
        int row = idx >> 3, ch = idx & 7;
        const __half* g = quh + (long)(i0 + row) * VDIM + h * DH + ch * 8;
        CP16(qsA + (uint32_t)(row * 144 + ch * 16), g);
    }
    CP_COMMIT();
    load_kv(0, 0);
    asm volatile("cp.async.wait_group 0;" ::: "memory");
    __syncthreads();

    uint32_t quA[4][4];
#pragma unroll
    for (int kc = 0; kc < 4; kc++) {
        quA[kc][0] = *(const uint32_t*)&qs[(w * 16 + lq) * 72 + kc * 16 + 2 * lr];
        quA[kc][1] = *(const uint32_t*)&qs[(w * 16 + lq + 8) * 72 + kc * 16 + 2 * lr];
        quA[kc][2] = *(const uint32_t*)&qs[(w * 16 + lq) * 72 + kc * 16 + 2 * lr + 8];
        quA[kc][3] = *(const uint32_t*)&qs[(w * 16 + lq + 8) * 72 + kc * 16 + 2 * lr + 8];
    }

    float O[8][4];
#pragma unroll
    for (int i = 0; i < 8; i++)
#pragma unroll
        for (int q = 0; q < 4; q++) O[i][q] = 0.f;
    float m0 = -1e30f, m1 = -1e30f, l0 = 0.f, l1 = 0.f;

    const float* qp0 = QP + ((long)h * S + r0g) * S;
    const float* qp1 = qp0 + 8 * S;

    for (int jt = 0; jt <= br; jt++) {
        if (jt < br) {
            load_kv(jt + 1, (jt + 1) & 1);
            asm volatile("cp.async.wait_group 1;" ::: "memory");
        } else {
            asm volatile("cp.async.wait_group 0;" ::: "memory");
        }
        __syncthreads();

        const __half* ksb = ks + (jt & 1) * (128 * 72);
        const __half* vsb = vs + (jt & 1) * (64 * 136);
        const int j0 = jt * 128;

        float s[16][4];
#pragma unroll
        for (int i = 0; i < 16; i++)
#pragma unroll
            for (int q = 0; q < 4; q++) s[i][q] = 0.f;

#pragma unroll
        for (int kc = 0; kc < 4; kc++)
#pragma unroll
            for (int nt = 0; nt < 16; nt++) {
                uint32_t bb[2];
                bb[0] = *(const uint32_t*)&ksb[(nt * 8 + lq) * 72 + kc * 16 + 2 * lr];
                bb[1] = *(const uint32_t*)&ksb[(nt * 8 + lq) * 72 + kc * 16 + 2 * lr + 8];
                mma_f16_16x8x16(s[nt], quA[kc], bb);
            }

        {
            const int b0 = j0 - r0g - 1 + 2 * S;
            const int b1 = b0 - 8;
#pragma unroll
            for (int nt = 0; nt < 16; nt++) {
                const int jA = nt * 8 + 2 * lr;
                s[nt][0] = (s[nt][0] + qp0[(b0 + jA) & (S - 1)]) * 0.125f;
                s[nt][1] = (s[nt][1] + qp0[(b0 + jA + 1) & (S - 1)]) * 0.125f;
                s[nt][2] = (s[nt][2] + qp1[(b1 + jA) & (S - 1)]) * 0.125f;
                s[nt][3] = (s[nt][3] + qp1[(b1 + jA + 1) & (S - 1)]) * 0.125f;
            }
        }
        if (jt == br) {
#pragma unroll
            for (int nt = 0; nt < 16; nt++) {
                const int j = j0 + nt * 8 + 2 * lr;
                if (j > r0g)     s[nt][0] = -1e30f;
                if (j + 1 > r0g) s[nt][1] = -1e30f;
                if (j > r1g)     s[nt][2] = -1e30f;
                if (j + 1 > r1g) s[nt][3] = -1e30f;
            }
        }

        float mx0 = -1e30f, mx1 = -1e30f;
#pragma unroll
        for (int nt = 0; nt < 16; nt++) {
            mx0 = fmaxf(mx0, fmaxf(s[nt][0], s[nt][1]));
            mx1 = fmaxf(mx1, fmaxf(s[nt][2], s[nt][3]));
        }
        mx0 = fmaxf(mx0, __shfl_xor_sync(0xffffffffu, mx0, 1));
        mx0 = fmaxf(mx0, __shfl_xor_sync(0xffffffffu, mx0, 2));
        mx1 = fmaxf(mx1, __shfl_xor_sync(0xffffffffu, mx1, 1));
        mx1 = fmaxf(mx1, __shfl_xor_sync(0xffffffffu, mx1, 2));
        const float m0n = fmaxf(m0, mx0), m1n = fmaxf(m1, mx1);
        const float sc0 = __expf(m0 - m0n), sc1 = __expf(m1 - m1n);
        m0 = m0n; m1 = m1n;

        uint32_t pa[8][4];
        float rs0 = 0.f, rs1 = 0.f;
#pragma unroll
        for (int kc = 0; kc < 8; kc++) {
            float p00 = __expf(s[2 * kc][0] - m0),     p01 = __expf(s[2 * kc][1] - m0);
            float p02 = __expf(s[2 * kc][2] - m1),     p03 = __expf(s[2 * kc][3] - m1);
            float p10 = __expf(s[2 * kc + 1][0] - m0), p11 = __expf(s[2 * kc + 1][1] - m0);
            float p12 = __expf(s[2 * kc + 1][2] - m1), p13 = __expf(s[2 * kc + 1][3] - m1);
            rs0 += p00 + p01 + p10 + p11;
            rs1 += p02 + p03 + p12 + p13;
            *(__half2*)&pa[kc][0] = __floats2half2_rn(p00, p01);
            *(__half2*)&pa[kc][1] = __floats2half2_rn(p02, p03);
            *(__half2*)&pa[kc][2] = __floats2half2_rn(p10, p11);
            *(__half2*)&pa[kc][3] = __floats2half2_rn(p12, p13);
        }
        rs0 += __shfl_xor_sync(0xffffffffu, rs0, 1);
        rs0 += __shfl_xor_sync(0xffffffffu, rs0, 2);
        rs1 += __shfl_xor_sync(0xffffffffu, rs1, 1);
        rs1 += __shfl_xor_sync(0xffffffffu, rs1, 2);
        l0 = l0 * sc0 + rs0;
        l1 = l1 * sc1 + rs1;
#pragma unroll
        for (int nt = 0; nt < 8; nt++) {
            O[nt][0] *= sc0; O[nt][1] *= sc0;
            O[nt][2] *= sc1; O[nt][3] *= sc1;
        }

#pragma unroll
        for (int kc = 0; kc < 8; kc++)
#pragma unroll
            for (int nt = 0; nt < 8; nt++) {
                uint32_t bb[2];
                bb[0] = *(const uint32_t*)&vsb[(nt * 8 + lq) * 136 + kc * 16 + 2 * lr];
                bb[1] = *(const uint32_t*)&vsb[(nt * 8 + lq) * 136 + kc * 16 + 2 * lr + 8];
                mma_f16_16x8x16(O[nt], pa[kc], bb);
            }
        __syncthreads();
    }

    const float il0 = 1.f / l0, il1 = 1.f / l1;
#pragma unroll
    for (int nt = 0; nt < 8; nt++) {
        const int cc = h * DH + nt * 8 + 2 * lr;
        *(__half2*)&attnh[(long)r0g * VDIM + cc] =
            __floats2half2_rn(O[nt][0] * il0, O[nt][1] * il0);
        *(__half2*)&attnh[(long)r1g * VDIM + cc] =
            __floats2half2_rn(O[nt][2] * il1, O[nt][3] * il1);
    }
}

// ---------------------------------------------------------------------------
// aux: convert all fp32 inputs to fp16 in one launch
// ---------------------------------------------------------------------------
#define RN_X   (S * VDIM / 4)
#define RN_WQ  (3 * VDIM * VDIM / 4)
#define RN_WO  (VDIM * VDIM / 4)
#define RN_WP  (VDIM * VDIM / 4)
#define RN_RE  (S * VDIM / 4)
#define RN_TOT (RN_X + RN_WQ + RN_WO + RN_WP + RN_RE)
__global__ __launch_bounds__(256)
void cvt_all(const float* __restrict__ x, __half* __restrict__ xh,
             const float* __restrict__ wq, __half* __restrict__ wqh,
             const float* __restrict__ wo, __half* __restrict__ woh,
             const float* __restrict__ wp, __half* __restrict__ wph,
             const float* __restrict__ re, __half* __restrict__ reh)
{
    int i = blockIdx.x * blockDim.x + threadIdx.x;
    const float* src; __half* dst;
    if (i < RN_X)                       { src = x;  dst = xh; }
    else if ((i -= RN_X) < RN_WQ)       { src = wq; dst = wqh; }
    else if ((i -= RN_WQ) < RN_WO)      { src = wo; dst = woh; }
    else if ((i -= RN_WO) < RN_WP)      { src = wp; dst = wph; }
    else if ((i -= RN_WP) < RN_RE)      { src = re; dst = reh; }
    else return;
    float4 v = ((const float4*)src)[i];
    __half2* d = (__half2*)(dst + (size_t)i * 4);
    d[0] = __floats2half2_rn(v.x, v.y);
    d[1] = __floats2half2_rn(v.z, v.w);
}

// ---------------------------------------------------------------------------
extern "C" void kernel_launch(void* const* d_in, const int* in_sizes, int n_in,
                              void* d_out, int out_size)
{
    const float* x    = (const float*)d_in[0];
    const float* Wqkv = (const float*)d_in[1];
    const float* Wout = (const float*)d_in[2];
    const float* Wpos = (const float*)d_in[3];
    const float* uvec = (const float*)d_in[4];
    const float* vvec = (const float*)d_in[5];
    const float* rel  = (const float*)d_in[6];
    float* out = (float*)d_out;

    __half *xh, *wqkvh, *wouth, *wposh, *relh, *quh, *qvh, *kh, *relpjh, *vth, *attnh;
    float *QP;
    cudaGetSymbolAddress((void**)&xh,     g_xh);
    cudaGetSymbolAddress((void**)&wqkvh,  g_wqkvh);
    cudaGetSymbolAddress((void**)&wouth,  g_wouth);
    cudaGetSymbolAddress((void**)&wposh,  g_wposh);
    cudaGetSymbolAddress((void**)&relh,   g_relh);
    cudaGetSymbolAddress((void**)&quh,    g_quh);
    cudaGetSymbolAddress((void**)&qvh,    g_qvh);
    cudaGetSymbolAddress((void**)&kh,     g_kh);
    cudaGetSymbolAddress((void**)&relpjh, g_relpjh);
    cudaGetSymbolAddress((void**)&vth,    g_vth);
    cudaGetSymbolAddress((void**)&QP,     g_QP);
    cudaGetSymbolAddress((void**)&attnh,  g_attnh);

    const int SMEMG = STG * (128 + 128) * HP * 2;        // 61440
    const int SMEMF = (3 * 128 * 72 + 2 * 64 * 136) * 2; // 90112
    static bool attr_done = false;
    if (!attr_done) {
        cudaFuncSetAttribute(hgemm_nt<0, 0>, cudaFuncAttributeMaxDynamicSharedMemorySize, SMEMG);
        cudaFuncSetAttribute(hgemm_nt<0, 1>, cudaFuncAttributeMaxDynamicSharedMemorySize, SMEMG);
        cudaFuncSetAttribute(hgemm_nt<2, 0>, cudaFuncAttributeMaxDynamicSharedMemorySize, SMEMG);
        cudaFuncSetAttribute(hgemm_qkv,      cudaFuncAttributeMaxDynamicSharedMemorySize, SMEMG);
        cudaFuncSetAttribute(flash_attn,     cudaFuncAttributeMaxDynamicSharedMemorySize, SMEMF);
        attr_done = true;
    }

    const long SS = (long)S * S;

    // 1) convert all inputs to fp16
    cvt_all<<<(RN_TOT + 255) / 256, 256>>>(x, xh, Wqkv, wqkvh, Wout, wouth,
                                           Wpos, wposh, rel, relh);

    // 2) qkv GEMM with fused epilogue -> quh, qvh, kh, vth
    hgemm_qkv<<<dim3(24, 16, 1), 256, SMEMG>>>(xh, wqkvh, uvec, vvec,
                                               quh, qvh, kh, vth);

    // 3) relproj = rel @ Wpos^T  (fp16 out)
    hgemm_nt<0, 1><<<dim3(8, 16, 1), 256, SMEMG>>>(
        relh, VDIM, 0, wposh, VDIM, 0, relpjh, VDIM, 0, VDIM);

    // 4) QP[h] = qv_h @ rel_h^T  (anti-upper tiles; fp32 out)
    hgemm_nt<2, 0><<<dim3(136, 1, 16), 256, SMEMG>>>(
        qvh, VDIM, DH, relpjh, VDIM, DH, QP, S, SS, DH);

    // 5) fused flash attention
    flash_attn<<<dim3(256), 256, SMEMF>>>(quh, kh, vth, QP, attnh);

    // 6) out = attn @ Wout^T  (fp32 out)
    hgemm_nt<0, 0><<<dim3(8, 16, 1), 256, SMEMG>>>(
        attnh, VDIM, 0, wouth, VDIM, 0, out, VDIM, 0, VDIM);
}